// round 1
// baseline (speedup 1.0000x reference)
#include <cuda_runtime.h>
#include <math.h>

#define NPTS 65536
#define NS 16
#define C 256
#define C2 32
#define MTOT (NPTS*NS)
#define EPS 1e-5f

// ---------------- scratch (device globals; no allocation allowed) ----------------
__device__ float g_xq[NPTS*C];
__device__ float g_xk[NPTS*C];
__device__ float g_xv[NPTS*C];
__device__ float g_w2[NPTS*NS*C2];
__device__ float g_wcat[768*256];
__device__ float g_bcat[768];

__device__ float g_sum_p[3],  g_ssq_p[3];
__device__ float g_sum_1[C],  g_ssq_1[C];
__device__ float g_sum_2[C2], g_ssq_2[C2];
__device__ float g_bnp_s[3],  g_bnp_h[3];
__device__ float g_bn1_s[C],  g_bn1_h[C];
__device__ float g_bn2_s[C2], g_bn2_h[C2];

// ---------------- prep: concat qkv weights/biases, zero stats ----------------
__global__ void k_prep(const float* __restrict__ wq, const float* __restrict__ bq,
                       const float* __restrict__ wk, const float* __restrict__ bk,
                       const float* __restrict__ wv, const float* __restrict__ bv) {
    int t = blockIdx.x * blockDim.x + threadIdx.x;
    if (t < 768*256) {
        int o = t >> 8, k = t & 255;
        float v;
        if (o < 256)      v = wq[o*256 + k];
        else if (o < 512) v = wk[(o-256)*256 + k];
        else              v = wv[(o-512)*256 + k];
        g_wcat[t] = v;
    }
    if (t < 768) g_bcat[t] = (t < 256) ? bq[t] : (t < 512 ? bk[t-256] : bv[t-512]);
    if (t < 3)  { g_sum_p[t] = 0.f; g_ssq_p[t] = 0.f; }
    if (t < C)  { g_sum_1[t] = 0.f; g_ssq_1[t] = 0.f; }
    if (t < C2) { g_sum_2[t] = 0.f; g_ssq_2[t] = 0.f; }
}

// ---------------- K1: qkv SGEMM  O[N,768] = x[N,256] @ wcat[768,256]^T ----------------
__global__ __launch_bounds__(256) void k_qkv(const float* __restrict__ x) {
    __shared__ float As[16][132];
    __shared__ float Bs[16][132];
    const int tid = threadIdx.x;
    const int tx = tid & 15, ty = tid >> 4;
    const int m0 = blockIdx.y * 128;
    const int n0 = blockIdx.x * 128;

    float acc[8][8];
#pragma unroll
    for (int ii = 0; ii < 8; ii++)
#pragma unroll
        for (int jj = 0; jj < 8; jj++) acc[ii][jj] = 0.f;

    const int lrow = tid >> 2;
    const int lk4  = (tid & 3) << 2;

    for (int k0 = 0; k0 < 256; k0 += 16) {
#pragma unroll
        for (int h = 0; h < 2; h++) {
            int r = lrow + h*64;
            float4 va = *(const float4*)(x + (size_t)(m0 + r)*256 + k0 + lk4);
            As[lk4+0][r] = va.x; As[lk4+1][r] = va.y; As[lk4+2][r] = va.z; As[lk4+3][r] = va.w;
            float4 vb = *(const float4*)(g_wcat + (size_t)(n0 + r)*256 + k0 + lk4);
            Bs[lk4+0][r] = vb.x; Bs[lk4+1][r] = vb.y; Bs[lk4+2][r] = vb.z; Bs[lk4+3][r] = vb.w;
        }
        __syncthreads();
#pragma unroll
        for (int k = 0; k < 16; k++) {
            float a[8], b[8];
            *(float4*)&a[0] = *(const float4*)&As[k][ty*4];
            *(float4*)&a[4] = *(const float4*)&As[k][ty*4 + 64];
            *(float4*)&b[0] = *(const float4*)&Bs[k][tx*4];
            *(float4*)&b[4] = *(const float4*)&Bs[k][tx*4 + 64];
#pragma unroll
            for (int ii = 0; ii < 8; ii++)
#pragma unroll
                for (int jj = 0; jj < 8; jj++) acc[ii][jj] += a[ii]*b[jj];
        }
        __syncthreads();
    }

    const int region = n0 >> 8;
    float* dst = (region == 0) ? g_xq : ((region == 1) ? g_xk : g_xv);
    const int cb = n0 & 255;
    float bias[8];
#pragma unroll
    for (int jj = 0; jj < 8; jj++)
        bias[jj] = g_bcat[n0 + tx*4 + ((jj >> 2) << 6) + (jj & 3)];
#pragma unroll
    for (int ii = 0; ii < 8; ii++) {
        int row = m0 + ty*4 + (ii & 3) + ((ii >> 2) << 6);
#pragma unroll
        for (int jh = 0; jh < 2; jh++) {
            float4 o;
            o.x = acc[ii][jh*4+0] + bias[jh*4+0];
            o.y = acc[ii][jh*4+1] + bias[jh*4+1];
            o.z = acc[ii][jh*4+2] + bias[jh*4+2];
            o.w = acc[ii][jh*4+3] + bias[jh*4+3];
            *(float4*)(dst + (size_t)row*256 + cb + tx*4 + (jh << 6)) = o;
        }
    }
}

// ---------------- K2: BNp stats over v3 = (p[nb]-p[i])@wp1^T + bp1 ----------------
__global__ void k_statp(const float* __restrict__ p, const int* __restrict__ idx,
                        const float* __restrict__ wp1, const float* __restrict__ bp1) {
    float W[9], B[3];
#pragma unroll
    for (int q = 0; q < 9; q++) W[q] = wp1[q];
#pragma unroll
    for (int q = 0; q < 3; q++) B[q] = bp1[q];

    float s[3] = {0.f,0.f,0.f}, ss[3] = {0.f,0.f,0.f};
    int stride = gridDim.x * blockDim.x;
    for (int m = blockIdx.x * blockDim.x + threadIdx.x; m < MTOT; m += stride) {
        int i = m >> 4;
        int nb = idx[m];
        float d0 = p[nb*3+0] - p[i*3+0];
        float d1 = p[nb*3+1] - p[i*3+1];
        float d2 = p[nb*3+2] - p[i*3+2];
#pragma unroll
        for (int d = 0; d < 3; d++) {
            float v = W[d*3+0]*d0 + W[d*3+1]*d1 + W[d*3+2]*d2 + B[d];
            s[d] += v; ss[d] += v*v;
        }
    }
#pragma unroll
    for (int off = 16; off > 0; off >>= 1) {
#pragma unroll
        for (int d = 0; d < 3; d++) {
            s[d]  += __shfl_down_sync(0xffffffffu, s[d],  off);
            ss[d] += __shfl_down_sync(0xffffffffu, ss[d], off);
        }
    }
    if ((threadIdx.x & 31) == 0) {
#pragma unroll
        for (int d = 0; d < 3; d++) {
            atomicAdd(&g_sum_p[d], s[d]);
            atomicAdd(&g_ssq_p[d], ss[d]);
        }
    }
}

__global__ void k_finp(const float* __restrict__ gp, const float* __restrict__ btp) {
    int t = threadIdx.x;
    if (t < 3) {
        const float invM = 1.f / (float)MTOT;
        float mean = g_sum_p[t] * invM;
        float var  = fmaxf(g_ssq_p[t] * invM - mean*mean, 0.f);
        float sc   = gp[t] * rsqrtf(var + EPS);
        g_bnp_s[t] = sc; g_bnp_h[t] = btp[t] - mean*sc;
    }
}

// ---------------- K4: BN1 stats over w = xk[nb] - xq[i] + p_r ----------------
__global__ __launch_bounds__(256) void k_stat1(const float* __restrict__ p, const int* __restrict__ idx,
                                               const float* __restrict__ wp1, const float* __restrict__ bp1,
                                               const float* __restrict__ wp2, const float* __restrict__ bp2) {
    __shared__ int   sIdx[NS];
    __shared__ float sR3[NS][3];
    __shared__ float sPi[3];
    const int t = threadIdx.x;
    const float w20 = wp2[t*3+0], w21 = wp2[t*3+1], w22 = wp2[t*3+2], bpc = bp2[t];
    float accs = 0.f, accss = 0.f;
    const int i0 = blockIdx.x * 16;

    for (int ip = 0; ip < 16; ip++) {
        int i = i0 + ip;
        __syncthreads();
        if (t < NS) sIdx[t] = idx[i*NS + t];
        if (t >= 32 && t < 35) sPi[t-32] = p[i*3 + t - 32];
        __syncthreads();
        if (t < 48) {
            int j = t / 3, d = t % 3;
            int nb = sIdx[j];
            float d0 = p[nb*3+0]-sPi[0], d1 = p[nb*3+1]-sPi[1], d2 = p[nb*3+2]-sPi[2];
            float v = wp1[d*3+0]*d0 + wp1[d*3+1]*d1 + wp1[d*3+2]*d2 + bp1[d];
            v = g_bnp_s[d]*v + g_bnp_h[d];
            sR3[j][d] = fmaxf(v, 0.f);
        }
        __syncthreads();
        float xqc = g_xq[(size_t)i*C + t];
#pragma unroll
        for (int j = 0; j < NS; j++) {
            int nb = sIdx[j];
            float pr = w20*sR3[j][0] + w21*sR3[j][1] + w22*sR3[j][2] + bpc;
            float w = g_xk[(size_t)nb*C + t] - xqc + pr;
            accs += w; accss += w*w;
        }
    }
    atomicAdd(&g_sum_1[t], accs);
    atomicAdd(&g_ssq_1[t], accss);
}

__global__ void k_fin1(const float* __restrict__ g1, const float* __restrict__ b1) {
    int t = threadIdx.x;
    const float invM = 1.f / (float)MTOT;
    float mean = g_sum_1[t] * invM;
    float var  = fmaxf(g_ssq_1[t] * invM - mean*mean, 0.f);
    float sc   = g1[t] * rsqrtf(var + EPS);
    g_bn1_s[t] = sc; g_bn1_h[t] = b1[t] - mean*sc;
}

// ---------------- K6: w2 = relu(bn1(w)) @ ww1^T + bw1 ; BN2 stats ----------------
// dyn smem layout (floats): sWw1[8192] | sW[32*260] | sOut[32*33] | sXq[512] | sR3[96] | sRed[256] | sIdx[32](int)
#define K6_SMEM_FLOATS (8192 + 32*260 + 32*33 + 512 + 96 + 256 + 32)
__global__ __launch_bounds__(256) void k_w2(const float* __restrict__ p, const int* __restrict__ idx,
                                            const float* __restrict__ wp1, const float* __restrict__ bp1,
                                            const float* __restrict__ wp2, const float* __restrict__ bp2,
                                            const float* __restrict__ ww1, const float* __restrict__ bw1) {
    extern __shared__ float sm[];
    float* sWw1 = sm;
    float* sW   = sm + 8192;
    float* sOut = sW + 32*260;
    float* sXq  = sOut + 32*33;
    float* sR3  = sXq + 512;
    float* sRed = sR3 + 96;
    int*   sIdx = (int*)(sRed + 256);

    const int t = threadIdx.x;
    const int lane = t & 31, warp = t >> 5;

    for (int r = t; r < 2048; r += 256)
        ((float4*)sWw1)[r] = ((const float4*)ww1)[r];

    const float w20 = wp2[t*3+0], w21 = wp2[t*3+1], w22 = wp2[t*3+2], bpc = bp2[t];
    const float s1 = g_bn1_s[t], h1 = g_bn1_h[t];
    const float bwv = bw1[t & 31];
    float acc2s = 0.f, acc2ss = 0.f;
    const int i0 = blockIdx.x * 32;

    for (int pp = 0; pp < 16; pp++) {
        const int iA = i0 + pp*2;
        __syncthreads();
        if (t < 32) sIdx[t] = idx[iA*NS + t];
        sXq[t]       = g_xq[(size_t)iA*C + t];
        sXq[256 + t] = g_xq[(size_t)(iA+1)*C + t];
        __syncthreads();
        if (t < 96) {
            int j = t / 3, d = t % 3;
            int i = iA + (j >> 4);
            int nb = sIdx[j];
            float d0 = p[nb*3+0]-p[i*3+0], d1 = p[nb*3+1]-p[i*3+1], d2 = p[nb*3+2]-p[i*3+2];
            float v = wp1[d*3+0]*d0 + wp1[d*3+1]*d1 + wp1[d*3+2]*d2 + bp1[d];
            v = g_bnp_s[d]*v + g_bnp_h[d];
            sR3[j*3 + d] = fmaxf(v, 0.f);
        }
        __syncthreads();
#pragma unroll 8
        for (int row = 0; row < 32; row++) {
            int nb = sIdx[row];
            float pr = w20*sR3[row*3+0] + w21*sR3[row*3+1] + w22*sR3[row*3+2] + bpc;
            float w = g_xk[(size_t)nb*C + t] - sXq[((row >> 4) << 8) + t] + pr;
            sW[row*260 + t] = fmaxf(s1*w + h1, 0.f);
        }
        __syncthreads();
        // GEMM: warp -> 4 output channels (broadcast B), lane -> row
        {
            float a0 = 0.f, a1 = 0.f, a2 = 0.f, a3 = 0.f;
            const float4* rp = (const float4*)(sW + lane*260);
            const float4* q0 = (const float4*)(sWw1 + (warp*4+0)*256);
            const float4* q1 = (const float4*)(sWw1 + (warp*4+1)*256);
            const float4* q2 = (const float4*)(sWw1 + (warp*4+2)*256);
            const float4* q3 = (const float4*)(sWw1 + (warp*4+3)*256);
#pragma unroll
            for (int k4 = 0; k4 < 64; k4++) {
                float4 r = rp[k4];
                float4 b0 = q0[k4]; a0 += r.x*b0.x + r.y*b0.y + r.z*b0.z + r.w*b0.w;
                float4 b1v = q1[k4]; a1 += r.x*b1v.x + r.y*b1v.y + r.z*b1v.z + r.w*b1v.w;
                float4 b2v = q2[k4]; a2 += r.x*b2v.x + r.y*b2v.y + r.z*b2v.z + r.w*b2v.w;
                float4 b3v = q3[k4]; a3 += r.x*b3v.x + r.y*b3v.y + r.z*b3v.z + r.w*b3v.w;
            }
            sOut[lane*33 + warp*4 + 0] = a0;
            sOut[lane*33 + warp*4 + 1] = a1;
            sOut[lane*33 + warp*4 + 2] = a2;
            sOut[lane*33 + warp*4 + 3] = a3;
        }
        __syncthreads();
#pragma unroll
        for (int rep = 0; rep < 4; rep++) {
            int linear = rep*256 + t;
            float v = sOut[(linear >> 5)*33 + (linear & 31)] + bwv;
            g_w2[(size_t)iA*512 + linear] = v;
            acc2s += v; acc2ss += v*v;
        }
    }
    // reduce BN2 stats
    __syncthreads();
    sRed[t] = acc2s;
    __syncthreads();
    if (t < 32) {
        float s = 0.f;
#pragma unroll
        for (int r = 0; r < 8; r++) s += sRed[t + r*32];
        atomicAdd(&g_sum_2[t], s);
    }
    __syncthreads();
    sRed[t] = acc2ss;
    __syncthreads();
    if (t < 32) {
        float s = 0.f;
#pragma unroll
        for (int r = 0; r < 8; r++) s += sRed[t + r*32];
        atomicAdd(&g_ssq_2[t], s);
    }
}

__global__ void k_fin2(const float* __restrict__ g2, const float* __restrict__ b2) {
    int t = threadIdx.x;
    if (t < C2) {
        const float invM = 1.f / (float)MTOT;
        float mean = g_sum_2[t] * invM;
        float var  = fmaxf(g_ssq_2[t] * invM - mean*mean, 0.f);
        float sc   = g2[t] * rsqrtf(var + EPS);
        g_bn2_s[t] = sc; g_bn2_h[t] = b2[t] - mean*sc;
    }
}

// ---------------- K8: bn2->relu->ww2->softmax->weighted sum ----------------
__global__ __launch_bounds__(256) void k_out(const float* __restrict__ p, const int* __restrict__ idx,
                                             const float* __restrict__ wp1, const float* __restrict__ bp1,
                                             const float* __restrict__ wp2, const float* __restrict__ bp2,
                                             const float* __restrict__ ww2, const float* __restrict__ bw2,
                                             float* __restrict__ out) {
    __shared__ float sWw2[32][33];
    __shared__ float sU[16][33];
    __shared__ float sW3[16][33];
    __shared__ int   sIdx[16];
    __shared__ float sR3[16][3];
    __shared__ float sPi[3];
    __shared__ float sBn2s[32], sBn2h[32], sBw2[32];

    const int t = threadIdx.x;
#pragma unroll
    for (int rep = 0; rep < 4; rep++) {
        int linear = rep*256 + t;
        sWw2[linear >> 5][linear & 31] = ww2[linear];
    }
    if (t < 32) { sBn2s[t] = g_bn2_s[t]; sBn2h[t] = g_bn2_h[t]; sBw2[t] = bw2[t]; }
    const float w20 = wp2[t*3+0], w21 = wp2[t*3+1], w22 = wp2[t*3+2], bpc = bp2[t];
    const int cm = t & 31;
    const int i0 = blockIdx.x * 8;

    for (int ip = 0; ip < 8; ip++) {
        const int i = i0 + ip;
        __syncthreads();
        if (t < NS) sIdx[t] = idx[i*NS + t];
        if (t >= 32 && t < 35) sPi[t-32] = p[i*3 + t - 32];
        __syncthreads();
        if (t < 48) {
            int j = t / 3, d = t % 3;
            int nb = sIdx[j];
            float d0 = p[nb*3+0]-sPi[0], d1 = p[nb*3+1]-sPi[1], d2 = p[nb*3+2]-sPi[2];
            float v = wp1[d*3+0]*d0 + wp1[d*3+1]*d1 + wp1[d*3+2]*d2 + bp1[d];
            v = g_bnp_s[d]*v + g_bnp_h[d];
            sR3[j][d] = fmaxf(v, 0.f);
        }
#pragma unroll
        for (int rep = 0; rep < 2; rep++) {
            int linear = rep*256 + t;
            int j = linear >> 5, oc = linear & 31;
            float v = g_w2[(size_t)i*512 + linear];
            sU[j][oc] = fmaxf(sBn2s[oc]*v + sBn2h[oc], 0.f);
        }
        __syncthreads();
#pragma unroll
        for (int rep = 0; rep < 2; rep++) {
            int linear = rep*256 + t;
            int j = linear >> 5, oc = linear & 31;
            float a = sBw2[oc];
#pragma unroll
            for (int k = 0; k < 32; k++) a += sU[j][k] * sWw2[oc][k];
            sW3[j][oc] = a;
        }
        __syncthreads();
        if (t < 32) {
            float mx = -1e30f;
#pragma unroll
            for (int j = 0; j < NS; j++) mx = fmaxf(mx, sW3[j][t]);
            float sum = 0.f;
#pragma unroll
            for (int j = 0; j < NS; j++) { float e = __expf(sW3[j][t] - mx); sW3[j][t] = e; sum += e; }
            float inv = 1.f / sum;
#pragma unroll
            for (int j = 0; j < NS; j++) sW3[j][t] *= inv;
        }
        __syncthreads();
        float acc = 0.f;
#pragma unroll
        for (int j = 0; j < NS; j++) {
            int nb = sIdx[j];
            float pr = w20*sR3[j][0] + w21*sR3[j][1] + w22*sR3[j][2] + bpc;
            acc += (g_xv[(size_t)nb*C + t] + pr) * sW3[j][cm];
        }
        out[(size_t)i*C + t] = acc;
    }
}

// ---------------- launch ----------------
extern "C" void kernel_launch(void* const* d_in, const int* in_sizes, int n_in,
                              void* d_out, int out_size) {
    const float* p   = (const float*)d_in[0];
    const float* x   = (const float*)d_in[1];
    const int*   idx = (const int*)d_in[2];
    const float* wq  = (const float*)d_in[3];
    const float* bq  = (const float*)d_in[4];
    const float* wk  = (const float*)d_in[5];
    const float* bk  = (const float*)d_in[6];
    const float* wv  = (const float*)d_in[7];
    const float* bv  = (const float*)d_in[8];
    const float* wp1 = (const float*)d_in[9];
    const float* bp1 = (const float*)d_in[10];
    const float* gp  = (const float*)d_in[11];
    const float* btp = (const float*)d_in[12];
    const float* wp2 = (const float*)d_in[13];
    const float* bp2 = (const float*)d_in[14];
    const float* g1  = (const float*)d_in[15];
    const float* b1  = (const float*)d_in[16];
    const float* ww1 = (const float*)d_in[17];
    const float* bw1 = (const float*)d_in[18];
    const float* g2  = (const float*)d_in[19];
    const float* b2  = (const float*)d_in[20];
    const float* ww2 = (const float*)d_in[21];
    const float* bw2 = (const float*)d_in[22];
    float* out = (float*)d_out;

    static bool attr_set = false;
    (void)attr_set;
    cudaFuncSetAttribute(k_w2, cudaFuncAttributeMaxDynamicSharedMemorySize,
                         K6_SMEM_FLOATS * (int)sizeof(float));

    k_prep<<<768, 256>>>(wq, bq, wk, bk, wv, bv);
    k_qkv<<<dim3(6, 512), 256>>>(x);
    k_statp<<<512, 256>>>(p, idx, wp1, bp1);
    k_finp<<<1, 32>>>(gp, btp);
    k_stat1<<<4096, 256>>>(p, idx, wp1, bp1, wp2, bp2);
    k_fin1<<<1, 256>>>(g1, b1);
    k_w2<<<2048, 256, K6_SMEM_FLOATS * sizeof(float)>>>(p, idx, wp1, bp1, wp2, bp2, ww1, bw1);
    k_fin2<<<1, 32>>>(g2, b2);
    k_out<<<8192, 256>>>(p, idx, wp1, bp1, wp2, bp2, ww2, bw2, out);
}

// round 2
// speedup vs baseline: 1.0036x; 1.0036x over previous
#include <cuda_runtime.h>
#include <math.h>

#define NPTS 65536
#define NS 16
#define C 256
#define C2 32
#define MTOT (NPTS*NS)
#define EPS 1e-5f

typedef unsigned long long ull;

// ---------------- packed fp32x2 helpers (FFMA2 path, sm_103a) ----------------
__device__ __forceinline__ ull pack2(float lo, float hi) {
    ull r; asm("mov.b64 %0, {%1, %2};" : "=l"(r) : "f"(lo), "f"(hi)); return r;
}
__device__ __forceinline__ void fma2(ull& d, ull a, ull b) {
    asm("fma.rn.f32x2 %0, %1, %2, %3;" : "=l"(d) : "l"(a), "l"(b), "l"(d));
}
__device__ __forceinline__ float2 unpack2(ull v) {
    float2 f; asm("mov.b64 {%0, %1}, %2;" : "=f"(f.x), "=f"(f.y) : "l"(v)); return f;
}

// ---------------- scratch (device globals; no allocation allowed) ----------------
__device__ float g_xq[NPTS*C];
__device__ float g_xk[NPTS*C];
__device__ float g_xv[NPTS*C];
__device__ float g_w2[NPTS*NS*C2];
__device__ float g_wcat[768*256];
__device__ float g_bcat[768];

__device__ float g_sum_p[3],  g_ssq_p[3];
__device__ float g_sum_1[C],  g_ssq_1[C];
__device__ float g_sum_2[C2], g_ssq_2[C2];
__device__ float g_bnp_s[3],  g_bnp_h[3];
__device__ float g_bn1_s[C],  g_bn1_h[C];
__device__ float g_bn2_s[C2], g_bn2_h[C2];

// ---------------- prep: concat qkv weights/biases, zero stats ----------------
__global__ void k_prep(const float* __restrict__ wq, const float* __restrict__ bq,
                       const float* __restrict__ wk, const float* __restrict__ bk,
                       const float* __restrict__ wv, const float* __restrict__ bv) {
    int t = blockIdx.x * blockDim.x + threadIdx.x;
    if (t < 768*256) {
        int o = t >> 8, k = t & 255;
        float v;
        if (o < 256)      v = wq[o*256 + k];
        else if (o < 512) v = wk[(o-256)*256 + k];
        else              v = wv[(o-512)*256 + k];
        g_wcat[t] = v;
    }
    if (t < 768) g_bcat[t] = (t < 256) ? bq[t] : (t < 512 ? bk[t-256] : bv[t-512]);
    if (t < 3)  { g_sum_p[t] = 0.f; g_ssq_p[t] = 0.f; }
    if (t < C)  { g_sum_1[t] = 0.f; g_ssq_1[t] = 0.f; }
    if (t < C2) { g_sum_2[t] = 0.f; g_ssq_2[t] = 0.f; }
}

// ---------------- BNp stats over v3 = (p[nb]-p[i])@wp1^T + bp1 ----------------
__global__ void k_statp(const float* __restrict__ p, const int* __restrict__ idx,
                        const float* __restrict__ wp1, const float* __restrict__ bp1) {
    float W[9], B[3];
#pragma unroll
    for (int q = 0; q < 9; q++) W[q] = wp1[q];
#pragma unroll
    for (int q = 0; q < 3; q++) B[q] = bp1[q];

    float s[3] = {0.f,0.f,0.f}, ss[3] = {0.f,0.f,0.f};
    int stride = gridDim.x * blockDim.x;
    for (int m = blockIdx.x * blockDim.x + threadIdx.x; m < MTOT; m += stride) {
        int i = m >> 4;
        int nb = idx[m];
        float d0 = p[nb*3+0] - p[i*3+0];
        float d1 = p[nb*3+1] - p[i*3+1];
        float d2 = p[nb*3+2] - p[i*3+2];
#pragma unroll
        for (int d = 0; d < 3; d++) {
            float v = W[d*3+0]*d0 + W[d*3+1]*d1 + W[d*3+2]*d2 + B[d];
            s[d] += v; ss[d] += v*v;
        }
    }
#pragma unroll
    for (int off = 16; off > 0; off >>= 1) {
#pragma unroll
        for (int d = 0; d < 3; d++) {
            s[d]  += __shfl_down_sync(0xffffffffu, s[d],  off);
            ss[d] += __shfl_down_sync(0xffffffffu, ss[d], off);
        }
    }
    if ((threadIdx.x & 31) == 0) {
#pragma unroll
        for (int d = 0; d < 3; d++) {
            atomicAdd(&g_sum_p[d], s[d]);
            atomicAdd(&g_ssq_p[d], ss[d]);
        }
    }
}

__global__ void k_finp(const float* __restrict__ gp, const float* __restrict__ btp) {
    int t = threadIdx.x;
    if (t < 3) {
        const float invM = 1.f / (float)MTOT;
        float mean = g_sum_p[t] * invM;
        float var  = fmaxf(g_ssq_p[t] * invM - mean*mean, 0.f);
        float sc   = gp[t] * rsqrtf(var + EPS);
        g_bnp_s[t] = sc; g_bnp_h[t] = btp[t] - mean*sc;
    }
}

// ---------------- qkv SGEMM via FFMA2: O[N,768] = x[N,256] @ wcat[768,256]^T --------
__global__ __launch_bounds__(256) void k_qkv(const float* __restrict__ x) {
    __shared__ float As[16][132];
    __shared__ float Bs[16][132];
    const int tid = threadIdx.x;
    const int tx = tid & 15, ty = tid >> 4;
    const int m0 = blockIdx.y * 128;
    const int n0 = blockIdx.x * 128;

    // column-paired accumulators: acc2[ii][jj] holds cols (2jj, 2jj+1) of the
    // 8-col thread tile (layout: cols tx*4+{0..3} then +64)
    ull acc2[8][4];
#pragma unroll
    for (int ii = 0; ii < 8; ii++)
#pragma unroll
        for (int jj = 0; jj < 4; jj++) acc2[ii][jj] = 0ull;

    const int lrow = tid >> 2;
    const int lk4  = (tid & 3) << 2;

    for (int k0 = 0; k0 < 256; k0 += 16) {
#pragma unroll
        for (int h = 0; h < 2; h++) {
            int r = lrow + h*64;
            float4 va = *(const float4*)(x + (size_t)(m0 + r)*256 + k0 + lk4);
            As[lk4+0][r] = va.x; As[lk4+1][r] = va.y; As[lk4+2][r] = va.z; As[lk4+3][r] = va.w;
            float4 vb = *(const float4*)(g_wcat + (size_t)(n0 + r)*256 + k0 + lk4);
            Bs[lk4+0][r] = vb.x; Bs[lk4+1][r] = vb.y; Bs[lk4+2][r] = vb.z; Bs[lk4+3][r] = vb.w;
        }
        __syncthreads();
#pragma unroll
        for (int k = 0; k < 16; k++) {
            float a[8];
            *(float4*)&a[0] = *(const float4*)&As[k][ty*4];
            *(float4*)&a[4] = *(const float4*)&As[k][ty*4 + 64];
            ull b2[4];
            {
                ulonglong2 u0 = *(const ulonglong2*)&Bs[k][tx*4];
                ulonglong2 u1 = *(const ulonglong2*)&Bs[k][tx*4 + 64];
                b2[0] = u0.x; b2[1] = u0.y; b2[2] = u1.x; b2[3] = u1.y;
            }
            ull a2[8];
#pragma unroll
            for (int ii = 0; ii < 8; ii++) a2[ii] = pack2(a[ii], a[ii]);
#pragma unroll
            for (int ii = 0; ii < 8; ii++)
#pragma unroll
                for (int jj = 0; jj < 4; jj++) fma2(acc2[ii][jj], a2[ii], b2[jj]);
        }
        __syncthreads();
    }

    const int region = n0 >> 8;
    float* dst = (region == 0) ? g_xq : ((region == 1) ? g_xk : g_xv);
    const int cb = n0 & 255;
    float bias[8];
#pragma unroll
    for (int jj = 0; jj < 8; jj++)
        bias[jj] = g_bcat[n0 + tx*4 + ((jj >> 2) << 6) + (jj & 3)];
#pragma unroll
    for (int ii = 0; ii < 8; ii++) {
        int row = m0 + ty*4 + (ii & 3) + ((ii >> 2) << 6);
#pragma unroll
        for (int jh = 0; jh < 2; jh++) {
            float2 lo = unpack2(acc2[ii][jh*2 + 0]);
            float2 hi = unpack2(acc2[ii][jh*2 + 1]);
            float4 o;
            o.x = lo.x + bias[jh*4+0];
            o.y = lo.y + bias[jh*4+1];
            o.z = hi.x + bias[jh*4+2];
            o.w = hi.y + bias[jh*4+3];
            *(float4*)(dst + (size_t)row*256 + cb + tx*4 + (jh << 6)) = o;
        }
    }
}

// ---------------- BN1 stats over w = xk[nb] - xq[i] + p_r ----------------
__global__ __launch_bounds__(256) void k_stat1(const float* __restrict__ p, const int* __restrict__ idx,
                                               const float* __restrict__ wp1, const float* __restrict__ bp1,
                                               const float* __restrict__ wp2, const float* __restrict__ bp2) {
    __shared__ int   sIdx[NS];
    __shared__ float sR3[NS][3];
    __shared__ float sPi[3];
    const int t = threadIdx.x;
    const float w20 = wp2[t*3+0], w21 = wp2[t*3+1], w22 = wp2[t*3+2], bpc = bp2[t];
    float accs = 0.f, accss = 0.f;
    const int i0 = blockIdx.x * 16;

    for (int ip = 0; ip < 16; ip++) {
        int i = i0 + ip;
        __syncthreads();
        if (t < NS) sIdx[t] = idx[i*NS + t];
        if (t >= 32 && t < 35) sPi[t-32] = p[i*3 + t - 32];
        __syncthreads();
        if (t < 48) {
            int j = t / 3, d = t % 3;
            int nb = sIdx[j];
            float d0 = p[nb*3+0]-sPi[0], d1 = p[nb*3+1]-sPi[1], d2 = p[nb*3+2]-sPi[2];
            float v = wp1[d*3+0]*d0 + wp1[d*3+1]*d1 + wp1[d*3+2]*d2 + bp1[d];
            v = g_bnp_s[d]*v + g_bnp_h[d];
            sR3[j][d] = fmaxf(v, 0.f);
        }
        __syncthreads();
        float xqc = g_xq[(size_t)i*C + t];
#pragma unroll
        for (int j = 0; j < NS; j++) {
            int nb = sIdx[j];
            float pr = w20*sR3[j][0] + w21*sR3[j][1] + w22*sR3[j][2] + bpc;
            float w = g_xk[(size_t)nb*C + t] - xqc + pr;
            accs += w; accss += w*w;
        }
    }
    atomicAdd(&g_sum_1[t], accs);
    atomicAdd(&g_ssq_1[t], accss);
}

__global__ void k_fin1(const float* __restrict__ g1, const float* __restrict__ b1) {
    int t = threadIdx.x;
    const float invM = 1.f / (float)MTOT;
    float mean = g_sum_1[t] * invM;
    float var  = fmaxf(g_ssq_1[t] * invM - mean*mean, 0.f);
    float sc   = g1[t] * rsqrtf(var + EPS);
    g_bn1_s[t] = sc; g_bn1_h[t] = b1[t] - mean*sc;
}

// ---------------- w2 = relu(bn1(w)) @ ww1^T + bw1 ; BN2 stats ----------------
#define K6_SMEM_FLOATS (8192 + 32*260 + 32*33 + 512 + 96 + 256 + 32)
__global__ __launch_bounds__(256) void k_w2(const float* __restrict__ p, const int* __restrict__ idx,
                                            const float* __restrict__ wp1, const float* __restrict__ bp1,
                                            const float* __restrict__ wp2, const float* __restrict__ bp2,
                                            const float* __restrict__ ww1, const float* __restrict__ bw1) {
    extern __shared__ float sm[];
    float* sWw1 = sm;
    float* sW   = sm + 8192;
    float* sOut = sW + 32*260;
    float* sXq  = sOut + 32*33;
    float* sR3  = sXq + 512;
    float* sRed = sR3 + 96;
    int*   sIdx = (int*)(sRed + 256);

    const int t = threadIdx.x;
    const int lane = t & 31, warp = t >> 5;

    for (int r = t; r < 2048; r += 256)
        ((float4*)sWw1)[r] = ((const float4*)ww1)[r];

    const float w20 = wp2[t*3+0], w21 = wp2[t*3+1], w22 = wp2[t*3+2], bpc = bp2[t];
    const float s1 = g_bn1_s[t], h1 = g_bn1_h[t];
    const float bwv = bw1[t & 31];
    float acc2s = 0.f, acc2ss = 0.f;
    const int i0 = blockIdx.x * 32;

    for (int pp = 0; pp < 16; pp++) {
        const int iA = i0 + pp*2;
        __syncthreads();
        if (t < 32) sIdx[t] = idx[iA*NS + t];
        sXq[t]       = g_xq[(size_t)iA*C + t];
        sXq[256 + t] = g_xq[(size_t)(iA+1)*C + t];
        __syncthreads();
        if (t < 96) {
            int j = t / 3, d = t % 3;
            int i = iA + (j >> 4);
            int nb = sIdx[j];
            float d0 = p[nb*3+0]-p[i*3+0], d1 = p[nb*3+1]-p[i*3+1], d2 = p[nb*3+2]-p[i*3+2];
            float v = wp1[d*3+0]*d0 + wp1[d*3+1]*d1 + wp1[d*3+2]*d2 + bp1[d];
            v = g_bnp_s[d]*v + g_bnp_h[d];
            sR3[j*3 + d] = fmaxf(v, 0.f);
        }
        __syncthreads();
#pragma unroll 8
        for (int row = 0; row < 32; row++) {
            int nb = sIdx[row];
            float pr = w20*sR3[row*3+0] + w21*sR3[row*3+1] + w22*sR3[row*3+2] + bpc;
            float w = g_xk[(size_t)nb*C + t] - sXq[((row >> 4) << 8) + t] + pr;
            sW[row*260 + t] = fmaxf(s1*w + h1, 0.f);
        }
        __syncthreads();
        // GEMM via FFMA2: warp -> 4 output channels (broadcast B), lane -> row
        {
            ull p0 = 0ull, p1 = 0ull, p2 = 0ull, p3 = 0ull;
            const ulonglong2* rp = (const ulonglong2*)(sW + lane*260);
            const ulonglong2* q0 = (const ulonglong2*)(sWw1 + (warp*4+0)*256);
            const ulonglong2* q1 = (const ulonglong2*)(sWw1 + (warp*4+1)*256);
            const ulonglong2* q2 = (const ulonglong2*)(sWw1 + (warp*4+2)*256);
            const ulonglong2* q3 = (const ulonglong2*)(sWw1 + (warp*4+3)*256);
#pragma unroll 8
            for (int k4 = 0; k4 < 64; k4++) {
                ulonglong2 r = rp[k4];
                ulonglong2 b0 = q0[k4]; fma2(p0, r.x, b0.x); fma2(p0, r.y, b0.y);
                ulonglong2 b1v = q1[k4]; fma2(p1, r.x, b1v.x); fma2(p1, r.y, b1v.y);
                ulonglong2 b2v = q2[k4]; fma2(p2, r.x, b2v.x); fma2(p2, r.y, b2v.y);
                ulonglong2 b3v = q3[k4]; fma2(p3, r.x, b3v.x); fma2(p3, r.y, b3v.y);
            }
            float2 f0 = unpack2(p0), f1 = unpack2(p1), f2 = unpack2(p2), f3 = unpack2(p3);
            sOut[lane*33 + warp*4 + 0] = f0.x + f0.y;
            sOut[lane*33 + warp*4 + 1] = f1.x + f1.y;
            sOut[lane*33 + warp*4 + 2] = f2.x + f2.y;
            sOut[lane*33 + warp*4 + 3] = f3.x + f3.y;
        }
        __syncthreads();
#pragma unroll
        for (int rep = 0; rep < 4; rep++) {
            int linear = rep*256 + t;
            float v = sOut[(linear >> 5)*33 + (linear & 31)] + bwv;
            g_w2[(size_t)iA*512 + linear] = v;
            acc2s += v; acc2ss += v*v;
        }
    }
    // reduce BN2 stats
    __syncthreads();
    sRed[t] = acc2s;
    __syncthreads();
    if (t < 32) {
        float s = 0.f;
#pragma unroll
        for (int r = 0; r < 8; r++) s += sRed[t + r*32];
        atomicAdd(&g_sum_2[t], s);
    }
    __syncthreads();
    sRed[t] = acc2ss;
    __syncthreads();
    if (t < 32) {
        float s = 0.f;
#pragma unroll
        for (int r = 0; r < 8; r++) s += sRed[t + r*32];
        atomicAdd(&g_ssq_2[t], s);
    }
}

__global__ void k_fin2(const float* __restrict__ g2, const float* __restrict__ b2) {
    int t = threadIdx.x;
    if (t < C2) {
        const float invM = 1.f / (float)MTOT;
        float mean = g_sum_2[t] * invM;
        float var  = fmaxf(g_ssq_2[t] * invM - mean*mean, 0.f);
        float sc   = g2[t] * rsqrtf(var + EPS);
        g_bn2_s[t] = sc; g_bn2_h[t] = b2[t] - mean*sc;
    }
}

// ---------------- bn2->relu->ww2->softmax->weighted sum ----------------
__global__ __launch_bounds__(256) void k_out(const float* __restrict__ p, const int* __restrict__ idx,
                                             const float* __restrict__ wp1, const float* __restrict__ bp1,
                                             const float* __restrict__ wp2, const float* __restrict__ bp2,
                                             const float* __restrict__ ww2, const float* __restrict__ bw2,
                                             float* __restrict__ out) {
    __shared__ float sWw2[32][33];
    __shared__ float sU[16][33];
    __shared__ float sW3[16][33];
    __shared__ int   sIdx[16];
    __shared__ float sR3[16][3];
    __shared__ float sPi[3];
    __shared__ float sBn2s[32], sBn2h[32], sBw2[32];

    const int t = threadIdx.x;
#pragma unroll
    for (int rep = 0; rep < 4; rep++) {
        int linear = rep*256 + t;
        sWw2[linear >> 5][linear & 31] = ww2[linear];
    }
    if (t < 32) { sBn2s[t] = g_bn2_s[t]; sBn2h[t] = g_bn2_h[t]; sBw2[t] = bw2[t]; }
    const float w20 = wp2[t*3+0], w21 = wp2[t*3+1], w22 = wp2[t*3+2], bpc = bp2[t];
    const int cm = t & 31;
    const int i0 = blockIdx.x * 8;

    for (int ip = 0; ip < 8; ip++) {
        const int i = i0 + ip;
        __syncthreads();
        if (t < NS) sIdx[t] = idx[i*NS + t];
        if (t >= 32 && t < 35) sPi[t-32] = p[i*3 + t - 32];
        __syncthreads();
        if (t < 48) {
            int j = t / 3, d = t % 3;
            int nb = sIdx[j];
            float d0 = p[nb*3+0]-sPi[0], d1 = p[nb*3+1]-sPi[1], d2 = p[nb*3+2]-sPi[2];
            float v = wp1[d*3+0]*d0 + wp1[d*3+1]*d1 + wp1[d*3+2]*d2 + bp1[d];
            v = g_bnp_s[d]*v + g_bnp_h[d];
            sR3[j][d] = fmaxf(v, 0.f);
        }
#pragma unroll
        for (int rep = 0; rep < 2; rep++) {
            int linear = rep*256 + t;
            int j = linear >> 5, oc = linear & 31;
            float v = g_w2[(size_t)i*512 + linear];
            sU[j][oc] = fmaxf(sBn2s[oc]*v + sBn2h[oc], 0.f);
        }
        __syncthreads();
#pragma unroll
        for (int rep = 0; rep < 2; rep++) {
            int linear = rep*256 + t;
            int j = linear >> 5, oc = linear & 31;
            float a = sBw2[oc];
#pragma unroll
            for (int k = 0; k < 32; k++) a += sU[j][k] * sWw2[oc][k];
            sW3[j][oc] = a;
        }
        __syncthreads();
        if (t < 32) {
            float mx = -1e30f;
#pragma unroll
            for (int j = 0; j < NS; j++) mx = fmaxf(mx, sW3[j][t]);
            float sum = 0.f;
#pragma unroll
            for (int j = 0; j < NS; j++) { float e = __expf(sW3[j][t] - mx); sW3[j][t] = e; sum += e; }
            float inv = 1.f / sum;
#pragma unroll
            for (int j = 0; j < NS; j++) sW3[j][t] *= inv;
        }
        __syncthreads();
        float acc = 0.f;
#pragma unroll
        for (int j = 0; j < NS; j++) {
            int nb = sIdx[j];
            float pr = w20*sR3[j][0] + w21*sR3[j][1] + w22*sR3[j][2] + bpc;
            acc += (g_xv[(size_t)nb*C + t] + pr) * sW3[j][cm];
        }
        out[(size_t)i*C + t] = acc;
    }
}

// ---------------- launch ----------------
extern "C" void kernel_launch(void* const* d_in, const int* in_sizes, int n_in,
                              void* d_out, int out_size) {
    const float* p   = (const float*)d_in[0];
    const float* x   = (const float*)d_in[1];
    const int*   idx = (const int*)d_in[2];
    const float* wq  = (const float*)d_in[3];
    const float* bq  = (const float*)d_in[4];
    const float* wk  = (const float*)d_in[5];
    const float* bk  = (const float*)d_in[6];
    const float* wv  = (const float*)d_in[7];
    const float* bv  = (const float*)d_in[8];
    const float* wp1 = (const float*)d_in[9];
    const float* bp1 = (const float*)d_in[10];
    const float* gp  = (const float*)d_in[11];
    const float* btp = (const float*)d_in[12];
    const float* wp2 = (const float*)d_in[13];
    const float* bp2 = (const float*)d_in[14];
    const float* g1  = (const float*)d_in[15];
    const float* b1  = (const float*)d_in[16];
    const float* ww1 = (const float*)d_in[17];
    const float* bw1 = (const float*)d_in[18];
    const float* g2  = (const float*)d_in[19];
    const float* b2  = (const float*)d_in[20];
    const float* ww2 = (const float*)d_in[21];
    const float* bw2 = (const float*)d_in[22];
    float* out = (float*)d_out;

    cudaFuncSetAttribute(k_w2, cudaFuncAttributeMaxDynamicSharedMemorySize,
                         K6_SMEM_FLOATS * (int)sizeof(float));

    // order chosen so the ncu -s 5 -c 1 window lands on a big kernel (k_qkv)
    k_prep<<<768, 256>>>(wq, bq, wk, bk, wv, bv);
    k_statp<<<512, 256>>>(p, idx, wp1, bp1);
    k_finp<<<1, 32>>>(gp, btp);
    k_qkv<<<dim3(6, 512), 256>>>(x);
    k_stat1<<<4096, 256>>>(p, idx, wp1, bp1, wp2, bp2);
    k_fin1<<<1, 256>>>(g1, b1);
    k_w2<<<2048, 256, K6_SMEM_FLOATS * sizeof(float)>>>(p, idx, wp1, bp1, wp2, bp2, ww1, bw1);
    k_fin2<<<1, 32>>>(g2, b2);
    k_out<<<8192, 256>>>(p, idx, wp1, bp1, wp2, bp2, ww2, bw2, out);
}

// round 3
// speedup vs baseline: 1.0089x; 1.0052x over previous
#include <cuda_runtime.h>
#include <math.h>

#define NPTS 65536
#define NS 16
#define C 256
#define C2 32
#define MTOT (NPTS*NS)
#define EPS 1e-5f

typedef unsigned long long ull;

// ---------------- packed fp32x2 helpers (FFMA2 path, sm_103a) ----------------
__device__ __forceinline__ ull pack2(float lo, float hi) {
    ull r; asm("mov.b64 %0, {%1, %2};" : "=l"(r) : "f"(lo), "f"(hi)); return r;
}
__device__ __forceinline__ void fma2(ull& d, ull a, ull b) {
    asm("fma.rn.f32x2 %0, %1, %2, %3;" : "=l"(d) : "l"(a), "l"(b), "l"(d));
}
__device__ __forceinline__ float2 unpack2(ull v) {
    float2 f; asm("mov.b64 {%0, %1}, %2;" : "=f"(f.x), "=f"(f.y) : "l"(v)); return f;
}

// ---------------- scratch ----------------
__device__ float g_xq[NPTS*C];
__device__ float g_xk[NPTS*C];
__device__ float g_xv[NPTS*C];
__device__ float g_w2[NPTS*NS*C2];
__device__ float g_v3[MTOT*3];

__device__ float g_sum_p[3],  g_ssq_p[3];
__device__ float g_sum_1[C],  g_ssq_1[C];
__device__ float g_sum_2[C2], g_ssq_2[C2];

// ---------------- launch 1: zero stats ----------------
__global__ void k_zero() {
    int t = threadIdx.x;
    if (t < 3)  { g_sum_p[t] = 0.f; g_ssq_p[t] = 0.f; }
    if (t < C)  { g_sum_1[t] = 0.f; g_ssq_1[t] = 0.f; }
    if (t < C2) { g_sum_2[t] = 0.f; g_ssq_2[t] = 0.f; }
}

// ---------------- launch 2: qkv SGEMM (FFMA2) + fused statp/v3 ----------------
__global__ __launch_bounds__(256) void k_qkv_statp(
        const float* __restrict__ x, const float* __restrict__ p,
        const int* __restrict__ idx,
        const float* __restrict__ wq, const float* __restrict__ bq,
        const float* __restrict__ wk, const float* __restrict__ bk,
        const float* __restrict__ wv, const float* __restrict__ bv,
        const float* __restrict__ wp1, const float* __restrict__ bp1) {
    const int t = threadIdx.x;

    if (blockIdx.x == 6) {
        // ---- statp path: v3 = (p[nb]-p[i])@wp1^T + bp1; store + stats ----
        float W[9], B[3];
#pragma unroll
        for (int q = 0; q < 9; q++) W[q] = wp1[q];
#pragma unroll
        for (int q = 0; q < 3; q++) B[q] = bp1[q];
        float s[3] = {0.f,0.f,0.f}, ss[3] = {0.f,0.f,0.f};
        int gt = blockIdx.y * 256 + t;
        for (int m = gt; m < MTOT; m += 512*256) {
            int i = m >> 4;
            int nb = idx[m];
            float d0 = p[nb*3+0] - p[i*3+0];
            float d1 = p[nb*3+1] - p[i*3+1];
            float d2 = p[nb*3+2] - p[i*3+2];
#pragma unroll
            for (int d = 0; d < 3; d++) {
                float v = W[d*3+0]*d0 + W[d*3+1]*d1 + W[d*3+2]*d2 + B[d];
                g_v3[(size_t)m*3 + d] = v;
                s[d] += v; ss[d] += v*v;
            }
        }
#pragma unroll
        for (int off = 16; off > 0; off >>= 1) {
#pragma unroll
            for (int d = 0; d < 3; d++) {
                s[d]  += __shfl_down_sync(0xffffffffu, s[d],  off);
                ss[d] += __shfl_down_sync(0xffffffffu, ss[d], off);
            }
        }
        if ((t & 31) == 0) {
#pragma unroll
            for (int d = 0; d < 3; d++) {
                atomicAdd(&g_sum_p[d], s[d]);
                atomicAdd(&g_ssq_p[d], ss[d]);
            }
        }
        return;
    }

    // ---- GEMM path ----
    __shared__ float As[16][132];
    __shared__ float Bs[16][132];
    const int tx = t & 15, ty = t >> 4;
    const int m0 = blockIdx.y * 128;
    const int n0 = blockIdx.x * 128;

    const float* wsel; const float* bsel; float* dst;
    if (n0 < 256)      { wsel = wq; bsel = bq; dst = g_xq; }
    else if (n0 < 512) { wsel = wk; bsel = bk; dst = g_xk; }
    else               { wsel = wv; bsel = bv; dst = g_xv; }
    const int rb = n0 & 255;

    ull acc2[8][4];
#pragma unroll
    for (int ii = 0; ii < 8; ii++)
#pragma unroll
        for (int jj = 0; jj < 4; jj++) acc2[ii][jj] = 0ull;

    const int lrow = t >> 2;
    const int lk4  = (t & 3) << 2;

    for (int k0 = 0; k0 < 256; k0 += 16) {
#pragma unroll
        for (int h = 0; h < 2; h++) {
            int r = lrow + h*64;
            float4 va = *(const float4*)(x + (size_t)(m0 + r)*256 + k0 + lk4);
            As[lk4+0][r] = va.x; As[lk4+1][r] = va.y; As[lk4+2][r] = va.z; As[lk4+3][r] = va.w;
            float4 vb = *(const float4*)(wsel + (size_t)(rb + r)*256 + k0 + lk4);
            Bs[lk4+0][r] = vb.x; Bs[lk4+1][r] = vb.y; Bs[lk4+2][r] = vb.z; Bs[lk4+3][r] = vb.w;
        }
        __syncthreads();
#pragma unroll
        for (int k = 0; k < 16; k++) {
            float a[8];
            *(float4*)&a[0] = *(const float4*)&As[k][ty*4];
            *(float4*)&a[4] = *(const float4*)&As[k][ty*4 + 64];
            ull b2[4];
            {
                ulonglong2 u0 = *(const ulonglong2*)&Bs[k][tx*4];
                ulonglong2 u1 = *(const ulonglong2*)&Bs[k][tx*4 + 64];
                b2[0] = u0.x; b2[1] = u0.y; b2[2] = u1.x; b2[3] = u1.y;
            }
            ull a2[8];
#pragma unroll
            for (int ii = 0; ii < 8; ii++) a2[ii] = pack2(a[ii], a[ii]);
#pragma unroll
            for (int ii = 0; ii < 8; ii++)
#pragma unroll
                for (int jj = 0; jj < 4; jj++) fma2(acc2[ii][jj], a2[ii], b2[jj]);
        }
        __syncthreads();
    }

    float bias[8];
#pragma unroll
    for (int jj = 0; jj < 8; jj++)
        bias[jj] = bsel[rb + tx*4 + ((jj >> 2) << 6) + (jj & 3)];
#pragma unroll
    for (int ii = 0; ii < 8; ii++) {
        int row = m0 + ty*4 + (ii & 3) + ((ii >> 2) << 6);
#pragma unroll
        for (int jh = 0; jh < 2; jh++) {
            float2 lo = unpack2(acc2[ii][jh*2 + 0]);
            float2 hi = unpack2(acc2[ii][jh*2 + 1]);
            float4 o;
            o.x = lo.x + bias[jh*4+0];
            o.y = lo.y + bias[jh*4+1];
            o.z = hi.x + bias[jh*4+2];
            o.w = hi.y + bias[jh*4+3];
            *(float4*)(dst + (size_t)row*256 + rb + tx*4 + (jh << 6)) = o;
        }
    }
}

// ---------------- launch 3: BN1 stats (barrier-free) ----------------
__global__ __launch_bounds__(256) void k_stat1(const int* __restrict__ idx,
                                               const float* __restrict__ gp, const float* __restrict__ btp,
                                               const float* __restrict__ wp2, const float* __restrict__ bp2) {
    const int t = threadIdx.x;
    const float invM = 1.f / (float)MTOT;
    float bs0, bs1, bs2, bh0, bh1, bh2;
    {
        float m0 = g_sum_p[0]*invM, m1 = g_sum_p[1]*invM, m2 = g_sum_p[2]*invM;
        float v0 = fmaxf(g_ssq_p[0]*invM - m0*m0, 0.f);
        float v1 = fmaxf(g_ssq_p[1]*invM - m1*m1, 0.f);
        float v2 = fmaxf(g_ssq_p[2]*invM - m2*m2, 0.f);
        bs0 = gp[0]*rsqrtf(v0+EPS); bh0 = btp[0]-m0*bs0;
        bs1 = gp[1]*rsqrtf(v1+EPS); bh1 = btp[1]-m1*bs1;
        bs2 = gp[2]*rsqrtf(v2+EPS); bh2 = btp[2]-m2*bs2;
    }
    const float w20 = wp2[t*3+0], w21 = wp2[t*3+1], w22 = wp2[t*3+2], bpc = bp2[t];
    float accs = 0.f, accss = 0.f;
    const int i0 = blockIdx.x * 16;

    for (int ip = 0; ip < 16; ip++) {
        const int i = i0 + ip;
        float xqc = g_xq[(size_t)i*C + t];
        int nbv[16];
        const int4* ipp = (const int4*)(idx + i*NS);
#pragma unroll
        for (int q = 0; q < 4; q++) {
            int4 v = __ldg(ipp + q);
            nbv[q*4+0] = v.x; nbv[q*4+1] = v.y; nbv[q*4+2] = v.z; nbv[q*4+3] = v.w;
        }
        float4 vv[12];
        const float4* vp = (const float4*)(g_v3 + (size_t)i*48);
#pragma unroll
        for (int q = 0; q < 12; q++) vv[q] = __ldg(vp + q);
        const float* vf = (const float*)vv;
#pragma unroll
        for (int j = 0; j < NS; j++) {
            float r0 = fmaxf(bs0*vf[j*3+0] + bh0, 0.f);
            float r1 = fmaxf(bs1*vf[j*3+1] + bh1, 0.f);
            float r2 = fmaxf(bs2*vf[j*3+2] + bh2, 0.f);
            float pr = w20*r0 + w21*r1 + w22*r2 + bpc;
            float w = g_xk[(size_t)nbv[j]*C + t] - xqc + pr;
            accs += w; accss += w*w;
        }
    }
    atomicAdd(&g_sum_1[t], accs);
    atomicAdd(&g_ssq_1[t], accss);
}

// ---------------- launch 4: w2 = relu(bn1(w)) @ ww1^T + bw1 ; BN2 stats ----------------
#define K6_SMEM_FLOATS (8192 + 32*260 + 32*33 + 512 + 96 + 256 + 32)
__global__ __launch_bounds__(256) void k_w2(const int* __restrict__ idx,
                                            const float* __restrict__ gp, const float* __restrict__ btp,
                                            const float* __restrict__ wp2, const float* __restrict__ bp2,
                                            const float* __restrict__ ww1, const float* __restrict__ bw1,
                                            const float* __restrict__ g1, const float* __restrict__ b1) {
    extern __shared__ float sm[];
    float* sWw1 = sm;
    float* sW   = sm + 8192;
    float* sOut = sW + 32*260;
    float* sXq  = sOut + 32*33;
    float* sR3  = sXq + 512;
    float* sRed = sR3 + 96;
    int*   sIdx = (int*)(sRed + 256);

    const int t = threadIdx.x;
    const int lane = t & 31, warp = t >> 5;

    for (int r = t; r < 2048; r += 256)
        ((float4*)sWw1)[r] = ((const float4*)ww1)[r];

    const float invM = 1.f / (float)MTOT;
    float bs0, bs1, bs2, bh0, bh1, bh2;
    {
        float m0 = g_sum_p[0]*invM, m1 = g_sum_p[1]*invM, m2 = g_sum_p[2]*invM;
        float v0 = fmaxf(g_ssq_p[0]*invM - m0*m0, 0.f);
        float v1 = fmaxf(g_ssq_p[1]*invM - m1*m1, 0.f);
        float v2 = fmaxf(g_ssq_p[2]*invM - m2*m2, 0.f);
        bs0 = gp[0]*rsqrtf(v0+EPS); bh0 = btp[0]-m0*bs0;
        bs1 = gp[1]*rsqrtf(v1+EPS); bh1 = btp[1]-m1*bs1;
        bs2 = gp[2]*rsqrtf(v2+EPS); bh2 = btp[2]-m2*bs2;
    }
    float s1, h1;
    {
        float mean = g_sum_1[t]*invM;
        float var  = fmaxf(g_ssq_1[t]*invM - mean*mean, 0.f);
        s1 = g1[t]*rsqrtf(var+EPS); h1 = b1[t] - mean*s1;
    }
    const float w20 = wp2[t*3+0], w21 = wp2[t*3+1], w22 = wp2[t*3+2], bpc = bp2[t];
    const float bwv = bw1[lane];
    float acc2s = 0.f, acc2ss = 0.f;
    const int i0 = blockIdx.x * 32;

    for (int pp = 0; pp < 16; pp++) {
        const int iA = i0 + pp*2;
        __syncthreads();
        if (t < 32) sIdx[t] = idx[iA*NS + t];
        if (t < 96) {
            int d = t % 3;
            float sc = (d==0) ? bs0 : ((d==1) ? bs1 : bs2);
            float hh = (d==0) ? bh0 : ((d==1) ? bh1 : bh2);
            sR3[t] = fmaxf(sc * g_v3[(size_t)iA*48 + t] + hh, 0.f);
        }
        sXq[t]       = g_xq[(size_t)iA*C + t];
        sXq[256 + t] = g_xq[(size_t)(iA+1)*C + t];
        __syncthreads();
#pragma unroll 8
        for (int row = 0; row < 32; row++) {
            int nb = sIdx[row];
            float pr = w20*sR3[row*3+0] + w21*sR3[row*3+1] + w22*sR3[row*3+2] + bpc;
            float w = g_xk[(size_t)nb*C + t] - sXq[((row >> 4) << 8) + t] + pr;
            sW[row*260 + t] = fmaxf(s1*w + h1, 0.f);
        }
        __syncthreads();
        {
            ull p0 = 0ull, p1 = 0ull, p2 = 0ull, p3 = 0ull;
            const ulonglong2* rp = (const ulonglong2*)(sW + lane*260);
            const ulonglong2* q0 = (const ulonglong2*)(sWw1 + (warp*4+0)*256);
            const ulonglong2* q1 = (const ulonglong2*)(sWw1 + (warp*4+1)*256);
            const ulonglong2* q2 = (const ulonglong2*)(sWw1 + (warp*4+2)*256);
            const ulonglong2* q3 = (const ulonglong2*)(sWw1 + (warp*4+3)*256);
#pragma unroll 8
            for (int k4 = 0; k4 < 64; k4++) {
                ulonglong2 r = rp[k4];
                ulonglong2 b0 = q0[k4]; fma2(p0, r.x, b0.x); fma2(p0, r.y, b0.y);
                ulonglong2 b1v = q1[k4]; fma2(p1, r.x, b1v.x); fma2(p1, r.y, b1v.y);
                ulonglong2 b2v = q2[k4]; fma2(p2, r.x, b2v.x); fma2(p2, r.y, b2v.y);
                ulonglong2 b3v = q3[k4]; fma2(p3, r.x, b3v.x); fma2(p3, r.y, b3v.y);
            }
            float2 f0 = unpack2(p0), f1 = unpack2(p1), f2 = unpack2(p2), f3 = unpack2(p3);
            sOut[lane*33 + warp*4 + 0] = f0.x + f0.y;
            sOut[lane*33 + warp*4 + 1] = f1.x + f1.y;
            sOut[lane*33 + warp*4 + 2] = f2.x + f2.y;
            sOut[lane*33 + warp*4 + 3] = f3.x + f3.y;
        }
        __syncthreads();
#pragma unroll
        for (int rep = 0; rep < 4; rep++) {
            int linear = rep*256 + t;
            float v = sOut[(linear >> 5)*33 + (linear & 31)] + bwv;
            g_w2[(size_t)iA*512 + linear] = v;
            acc2s += v; acc2ss += v*v;
        }
    }
    __syncthreads();
    sRed[t] = acc2s;
    __syncthreads();
    if (t < 32) {
        float s = 0.f;
#pragma unroll
        for (int r = 0; r < 8; r++) s += sRed[t + r*32];
        atomicAdd(&g_sum_2[t], s);
    }
    __syncthreads();
    sRed[t] = acc2ss;
    __syncthreads();
    if (t < 32) {
        float s = 0.f;
#pragma unroll
        for (int r = 0; r < 8; r++) s += sRed[t + r*32];
        atomicAdd(&g_ssq_2[t], s);
    }
}

// ---------------- launch 5: bn2->relu->ww2->softmax->weighted sum ----------------
__global__ __launch_bounds__(256) void k_out(const int* __restrict__ idx,
                                             const float* __restrict__ gp, const float* __restrict__ btp,
                                             const float* __restrict__ wp2, const float* __restrict__ bp2,
                                             const float* __restrict__ ww2, const float* __restrict__ bw2,
                                             const float* __restrict__ g2, const float* __restrict__ b2,
                                             float* __restrict__ out) {
    __shared__ float sWw2[32][33];
    __shared__ float sU[32][33];
    __shared__ float sW3[32][33];
    __shared__ int   sIdx[32];
    __shared__ float sR3[96];

    const int t = threadIdx.x;
    const int cm = t & 31;
#pragma unroll
    for (int rep = 0; rep < 4; rep++) {
        int linear = rep*256 + t;
        sWw2[linear >> 5][linear & 31] = ww2[linear];
    }
    const float invM = 1.f / (float)MTOT;
    float bs0, bs1, bs2, bh0, bh1, bh2;
    {
        float m0 = g_sum_p[0]*invM, m1 = g_sum_p[1]*invM, m2 = g_sum_p[2]*invM;
        float v0 = fmaxf(g_ssq_p[0]*invM - m0*m0, 0.f);
        float v1 = fmaxf(g_ssq_p[1]*invM - m1*m1, 0.f);
        float v2 = fmaxf(g_ssq_p[2]*invM - m2*m2, 0.f);
        bs0 = gp[0]*rsqrtf(v0+EPS); bh0 = btp[0]-m0*bs0;
        bs1 = gp[1]*rsqrtf(v1+EPS); bh1 = btp[1]-m1*bs1;
        bs2 = gp[2]*rsqrtf(v2+EPS); bh2 = btp[2]-m2*bs2;
    }
    float s2, h2;
    {
        float mean = g_sum_2[cm]*invM;
        float var  = fmaxf(g_ssq_2[cm]*invM - mean*mean, 0.f);
        s2 = g2[cm]*rsqrtf(var+EPS); h2 = b2[cm] - mean*s2;
    }
    const float w20 = wp2[t*3+0], w21 = wp2[t*3+1], w22 = wp2[t*3+2], bpc = bp2[t];
    const float bw2c = bw2[cm];
    const int i0 = blockIdx.x * 16;

    for (int pp = 0; pp < 8; pp++) {
        const int iA = i0 + pp*2;
        __syncthreads();
        if (t < 32) sIdx[t] = idx[iA*NS + t];
        if (t < 96) {
            int d = t % 3;
            float sc = (d==0) ? bs0 : ((d==1) ? bs1 : bs2);
            float hh = (d==0) ? bh0 : ((d==1) ? bh1 : bh2);
            sR3[t] = fmaxf(sc * g_v3[(size_t)iA*48 + t] + hh, 0.f);
        }
#pragma unroll
        for (int rep = 0; rep < 4; rep++) {
            int linear = rep*256 + t;
            float v = g_w2[(size_t)iA*512 + linear];
            sU[linear >> 5][cm] = fmaxf(s2*v + h2, 0.f);
        }
        __syncthreads();
#pragma unroll
        for (int rep = 0; rep < 4; rep++) {
            int linear = rep*256 + t;
            int j = linear >> 5;
            float a = bw2c;
#pragma unroll
            for (int k = 0; k < 32; k++) a += sU[j][k] * sWw2[cm][k];
            sW3[j][cm] = a;
        }
        __syncthreads();
        if (t < 64) {
            int pt = t >> 5, c = t & 31;
            int base = pt * 16;
            float mx = -1e30f;
#pragma unroll
            for (int j = 0; j < NS; j++) mx = fmaxf(mx, sW3[base+j][c]);
            float sum = 0.f;
#pragma unroll
            for (int j = 0; j < NS; j++) { float e = __expf(sW3[base+j][c] - mx); sW3[base+j][c] = e; sum += e; }
            float inv = 1.f / sum;
#pragma unroll
            for (int j = 0; j < NS; j++) sW3[base+j][c] *= inv;
        }
        __syncthreads();
#pragma unroll
        for (int pt = 0; pt < 2; pt++) {
            float acc = 0.f;
#pragma unroll
            for (int j = 0; j < NS; j++) {
                int rj = pt*16 + j;
                int nb = sIdx[rj];
                float pr = w20*sR3[rj*3+0] + w21*sR3[rj*3+1] + w22*sR3[rj*3+2] + bpc;
                acc += (g_xv[(size_t)nb*C + t] + pr) * sW3[rj][cm];
            }
            out[(size_t)(iA+pt)*C + t] = acc;
        }
    }
}

// ---------------- launch ----------------
extern "C" void kernel_launch(void* const* d_in, const int* in_sizes, int n_in,
                              void* d_out, int out_size) {
    const float* p   = (const float*)d_in[0];
    const float* x   = (const float*)d_in[1];
    const int*   idx = (const int*)d_in[2];
    const float* wq  = (const float*)d_in[3];
    const float* bq  = (const float*)d_in[4];
    const float* wk  = (const float*)d_in[5];
    const float* bk  = (const float*)d_in[6];
    const float* wv  = (const float*)d_in[7];
    const float* bv  = (const float*)d_in[8];
    const float* wp1 = (const float*)d_in[9];
    const float* bp1 = (const float*)d_in[10];
    const float* gp  = (const float*)d_in[11];
    const float* btp = (const float*)d_in[12];
    const float* wp2 = (const float*)d_in[13];
    const float* bp2 = (const float*)d_in[14];
    const float* g1  = (const float*)d_in[15];
    const float* b1  = (const float*)d_in[16];
    const float* ww1 = (const float*)d_in[17];
    const float* bw1 = (const float*)d_in[18];
    const float* g2  = (const float*)d_in[19];
    const float* b2  = (const float*)d_in[20];
    const float* ww2 = (const float*)d_in[21];
    const float* bw2 = (const float*)d_in[22];
    float* out = (float*)d_out;

    cudaFuncSetAttribute(k_w2, cudaFuncAttributeMaxDynamicSharedMemorySize,
                         K6_SMEM_FLOATS * (int)sizeof(float));

    k_zero<<<1, 256>>>();
    k_qkv_statp<<<dim3(7, 512), 256>>>(x, p, idx, wq, bq, wk, bk, wv, bv, wp1, bp1);
    k_stat1<<<4096, 256>>>(idx, gp, btp, wp2, bp2);
    k_w2<<<2048, 256, K6_SMEM_FLOATS * sizeof(float)>>>(idx, gp, btp, wp2, bp2, ww1, bw1, g1, b1);
    k_out<<<4096, 256>>>(idx, gp, btp, wp2, bp2, ww2, bw2, g2, b2, out);
}

// round 6
// speedup vs baseline: 1.0112x; 1.0024x over previous
#include <cuda_runtime.h>
#include <math.h>

#define NPTS 65536
#define NS 16
#define C 256
#define C2 32
#define MTOT (NPTS*NS)
#define EPS 1e-5f

typedef unsigned long long ull;

// ---------------- packed fp32x2 helpers (FFMA2 path, sm_103a) ----------------
__device__ __forceinline__ ull pack2(float lo, float hi) {
    ull r; asm("mov.b64 %0, {%1, %2};" : "=l"(r) : "f"(lo), "f"(hi)); return r;
}
__device__ __forceinline__ void fma2(ull& d, ull a, ull b) {
    asm("fma.rn.f32x2 %0, %1, %2, %3;" : "=l"(d) : "l"(a), "l"(b), "l"(d));
}
__device__ __forceinline__ float2 unpack2(ull v) {
    float2 f; asm("mov.b64 {%0, %1}, %2;" : "=f"(f.x), "=f"(f.y) : "l"(v)); return f;
}

// ---------------- scratch ----------------
__device__ float g_xq[NPTS*C];
__device__ float g_xk[NPTS*C];
__device__ float g_xv[NPTS*C];
__device__ float g_w2[NPTS*NS*C2];
__device__ float g_v3[MTOT*3];

__device__ float g_sum_p[3],  g_ssq_p[3];
__device__ float g_sum_1[C],  g_ssq_1[C];
__device__ float g_sum_2[C2], g_ssq_2[C2];

// ---------------- launch 1: zero stats ----------------
__global__ void k_zero() {
    int t = threadIdx.x;
    if (t < 3)  { g_sum_p[t] = 0.f; g_ssq_p[t] = 0.f; }
    if (t < C)  { g_sum_1[t] = 0.f; g_ssq_1[t] = 0.f; }
    if (t < C2) { g_sum_2[t] = 0.f; g_ssq_2[t] = 0.f; }
}

// ---------------- launch 2: qkv SGEMM (FFMA2) + fused statp/v3 ----------------
__global__ __launch_bounds__(256) void k_qkv_statp(
        const float* __restrict__ x, const float* __restrict__ p,
        const int* __restrict__ idx,
        const float* __restrict__ wq, const float* __restrict__ bq,
        const float* __restrict__ wk, const float* __restrict__ bk,
        const float* __restrict__ wv, const float* __restrict__ bv,
        const float* __restrict__ wp1, const float* __restrict__ bp1) {
    const int t = threadIdx.x;

    if (blockIdx.x == 6) {
        // ---- statp path: v3 = (p[nb]-p[i])@wp1^T + bp1; store + stats ----
        float W[9], B[3];
#pragma unroll
        for (int q = 0; q < 9; q++) W[q] = wp1[q];
#pragma unroll
        for (int q = 0; q < 3; q++) B[q] = bp1[q];
        float s[3] = {0.f,0.f,0.f}, ss[3] = {0.f,0.f,0.f};
        int gt = blockIdx.y * 256 + t;
        for (int m = gt; m < MTOT; m += 512*256) {
            int i = m >> 4;
            int nb = idx[m];
            float d0 = p[nb*3+0] - p[i*3+0];
            float d1 = p[nb*3+1] - p[i*3+1];
            float d2 = p[nb*3+2] - p[i*3+2];
#pragma unroll
            for (int d = 0; d < 3; d++) {
                float v = W[d*3+0]*d0 + W[d*3+1]*d1 + W[d*3+2]*d2 + B[d];
                g_v3[(size_t)m*3 + d] = v;
                s[d] += v; ss[d] += v*v;
            }
        }
#pragma unroll
        for (int off = 16; off > 0; off >>= 1) {
#pragma unroll
            for (int d = 0; d < 3; d++) {
                s[d]  += __shfl_down_sync(0xffffffffu, s[d],  off);
                ss[d] += __shfl_down_sync(0xffffffffu, ss[d], off);
            }
        }
        if ((t & 31) == 0) {
#pragma unroll
            for (int d = 0; d < 3; d++) {
                atomicAdd(&g_sum_p[d], s[d]);
                atomicAdd(&g_ssq_p[d], ss[d]);
            }
        }
        return;
    }

    // ---- GEMM path ----
    __shared__ float As[16][132];
    __shared__ float Bs[16][132];
    const int tx = t & 15, ty = t >> 4;
    const int m0 = blockIdx.y * 128;
    const int n0 = blockIdx.x * 128;

    const float* wsel; const float* bsel; float* dst;
    if (n0 < 256)      { wsel = wq; bsel = bq; dst = g_xq; }
    else if (n0 < 512) { wsel = wk; bsel = bk; dst = g_xk; }
    else               { wsel = wv; bsel = bv; dst = g_xv; }
    const int rb = n0 & 255;

    ull acc2[8][4];
#pragma unroll
    for (int ii = 0; ii < 8; ii++)
#pragma unroll
        for (int jj = 0; jj < 4; jj++) acc2[ii][jj] = 0ull;

    const int lrow = t >> 2;
    const int lk4  = (t & 3) << 2;

    for (int k0 = 0; k0 < 256; k0 += 16) {
#pragma unroll
        for (int h = 0; h < 2; h++) {
            int r = lrow + h*64;
            float4 va = *(const float4*)(x + (size_t)(m0 + r)*256 + k0 + lk4);
            As[lk4+0][r] = va.x; As[lk4+1][r] = va.y; As[lk4+2][r] = va.z; As[lk4+3][r] = va.w;
            float4 vb = *(const float4*)(wsel + (size_t)(rb + r)*256 + k0 + lk4);
            Bs[lk4+0][r] = vb.x; Bs[lk4+1][r] = vb.y; Bs[lk4+2][r] = vb.z; Bs[lk4+3][r] = vb.w;
        }
        __syncthreads();
#pragma unroll
        for (int k = 0; k < 16; k++) {
            float a[8];
            *(float4*)&a[0] = *(const float4*)&As[k][ty*4];
            *(float4*)&a[4] = *(const float4*)&As[k][ty*4 + 64];
            ull b2[4];
            {
                ulonglong2 u0 = *(const ulonglong2*)&Bs[k][tx*4];
                ulonglong2 u1 = *(const ulonglong2*)&Bs[k][tx*4 + 64];
                b2[0] = u0.x; b2[1] = u0.y; b2[2] = u1.x; b2[3] = u1.y;
            }
            ull a2[8];
#pragma unroll
            for (int ii = 0; ii < 8; ii++) a2[ii] = pack2(a[ii], a[ii]);
#pragma unroll
            for (int ii = 0; ii < 8; ii++)
#pragma unroll
                for (int jj = 0; jj < 4; jj++) fma2(acc2[ii][jj], a2[ii], b2[jj]);
        }
        __syncthreads();
    }

    float bias[8];
#pragma unroll
    for (int jj = 0; jj < 8; jj++)
        bias[jj] = bsel[rb + tx*4 + ((jj >> 2) << 6) + (jj & 3)];
#pragma unroll
    for (int ii = 0; ii < 8; ii++) {
        int row = m0 + ty*4 + (ii & 3) + ((ii >> 2) << 6);
#pragma unroll
        for (int jh = 0; jh < 2; jh++) {
            float2 lo = unpack2(acc2[ii][jh*2 + 0]);
            float2 hi = unpack2(acc2[ii][jh*2 + 1]);
            float4 o;
            o.x = lo.x + bias[jh*4+0];
            o.y = lo.y + bias[jh*4+1];
            o.z = hi.x + bias[jh*4+2];
            o.w = hi.y + bias[jh*4+3];
            *(float4*)(dst + (size_t)row*256 + rb + tx*4 + (jh << 6)) = o;
        }
    }
}

// ---------------- launch 3: BN1 stats (barrier-free) ----------------
__global__ __launch_bounds__(256) void k_stat1(const int* __restrict__ idx,
                                               const float* __restrict__ gp, const float* __restrict__ btp,
                                               const float* __restrict__ wp2, const float* __restrict__ bp2) {
    const int t = threadIdx.x;
    const float invM = 1.f / (float)MTOT;
    float bs0, bs1, bs2, bh0, bh1, bh2;
    {
        float m0 = g_sum_p[0]*invM, m1 = g_sum_p[1]*invM, m2 = g_sum_p[2]*invM;
        float v0 = fmaxf(g_ssq_p[0]*invM - m0*m0, 0.f);
        float v1 = fmaxf(g_ssq_p[1]*invM - m1*m1, 0.f);
        float v2 = fmaxf(g_ssq_p[2]*invM - m2*m2, 0.f);
        bs0 = gp[0]*rsqrtf(v0+EPS); bh0 = btp[0]-m0*bs0;
        bs1 = gp[1]*rsqrtf(v1+EPS); bh1 = btp[1]-m1*bs1;
        bs2 = gp[2]*rsqrtf(v2+EPS); bh2 = btp[2]-m2*bs2;
    }
    const float w20 = wp2[t*3+0], w21 = wp2[t*3+1], w22 = wp2[t*3+2], bpc = bp2[t];
    float accs = 0.f, accss = 0.f;
    const int i0 = blockIdx.x * 16;

    for (int ip = 0; ip < 16; ip++) {
        const int i = i0 + ip;
        float xqc = g_xq[(size_t)i*C + t];
        int nbv[16];
        const int4* ipp = (const int4*)(idx + i*NS);
#pragma unroll
        for (int q = 0; q < 4; q++) {
            int4 v = __ldg(ipp + q);
            nbv[q*4+0] = v.x; nbv[q*4+1] = v.y; nbv[q*4+2] = v.z; nbv[q*4+3] = v.w;
        }
        float4 vv[12];
        const float4* vp = (const float4*)(g_v3 + (size_t)i*48);
#pragma unroll
        for (int q = 0; q < 12; q++) vv[q] = __ldg(vp + q);
        const float* vf = (const float*)vv;
#pragma unroll
        for (int j = 0; j < NS; j++) {
            float r0 = fmaxf(bs0*vf[j*3+0] + bh0, 0.f);
            float r1 = fmaxf(bs1*vf[j*3+1] + bh1, 0.f);
            float r2 = fmaxf(bs2*vf[j*3+2] + bh2, 0.f);
            float pr = w20*r0 + w21*r1 + w22*r2 + bpc;
            float w = g_xk[(size_t)nbv[j]*C + t] - xqc + pr;
            accs += w; accss += w*w;
        }
    }
    atomicAdd(&g_sum_1[t], accs);
    atomicAdd(&g_ssq_1[t], accss);
}

// ---------------- launch 4: w2 = relu(bn1(w)) @ ww1^T + bw1 ; BN2 stats ----------------
#define K6_SMEM_FLOATS (8192 + 32*260 + 32*33 + 512 + 96 + 256 + 32)
__global__ __launch_bounds__(256) void k_w2(const int* __restrict__ idx,
                                            const float* __restrict__ gp, const float* __restrict__ btp,
                                            const float* __restrict__ wp2, const float* __restrict__ bp2,
                                            const float* __restrict__ ww1, const float* __restrict__ bw1,
                                            const float* __restrict__ g1, const float* __restrict__ b1) {
    extern __shared__ float sm[];
    float* sWw1 = sm;
    float* sW   = sm + 8192;
    float* sOut = sW + 32*260;
    float* sXq  = sOut + 32*33;
    float* sR3  = sXq + 512;
    float* sRed = sR3 + 96;
    int*   sIdx = (int*)(sRed + 256);

    const int t = threadIdx.x;
    const int lane = t & 31, warp = t >> 5;

    for (int r = t; r < 2048; r += 256)
        ((float4*)sWw1)[r] = ((const float4*)ww1)[r];

    const float invM = 1.f / (float)MTOT;
    float bs0, bs1, bs2, bh0, bh1, bh2;
    {
        float m0 = g_sum_p[0]*invM, m1 = g_sum_p[1]*invM, m2 = g_sum_p[2]*invM;
        float v0 = fmaxf(g_ssq_p[0]*invM - m0*m0, 0.f);
        float v1 = fmaxf(g_ssq_p[1]*invM - m1*m1, 0.f);
        float v2 = fmaxf(g_ssq_p[2]*invM - m2*m2, 0.f);
        bs0 = gp[0]*rsqrtf(v0+EPS); bh0 = btp[0]-m0*bs0;
        bs1 = gp[1]*rsqrtf(v1+EPS); bh1 = btp[1]-m1*bs1;
        bs2 = gp[2]*rsqrtf(v2+EPS); bh2 = btp[2]-m2*bs2;
    }
    float s1, h1;
    {
        float mean = g_sum_1[t]*invM;
        float var  = fmaxf(g_ssq_1[t]*invM - mean*mean, 0.f);
        s1 = g1[t]*rsqrtf(var+EPS); h1 = b1[t] - mean*s1;
    }
    const float w20 = wp2[t*3+0], w21 = wp2[t*3+1], w22 = wp2[t*3+2], bpc = bp2[t];
    const float bwv = bw1[lane];
    float acc2s = 0.f, acc2ss = 0.f;
    const int i0 = blockIdx.x * 32;

    for (int pp = 0; pp < 16; pp++) {
        const int iA = i0 + pp*2;
        __syncthreads();
        if (t < 32) sIdx[t] = idx[iA*NS + t];
        if (t < 96) {
            int d = t % 3;
            float sc = (d==0) ? bs0 : ((d==1) ? bs1 : bs2);
            float hh = (d==0) ? bh0 : ((d==1) ? bh1 : bh2);
            sR3[t] = fmaxf(sc * g_v3[(size_t)iA*48 + t] + hh, 0.f);
        }
        sXq[t]       = g_xq[(size_t)iA*C + t];
        sXq[256 + t] = g_xq[(size_t)(iA+1)*C + t];
        __syncthreads();
#pragma unroll 8
        for (int row = 0; row < 32; row++) {
            int nb = sIdx[row];
            float pr = w20*sR3[row*3+0] + w21*sR3[row*3+1] + w22*sR3[row*3+2] + bpc;
            float w = g_xk[(size_t)nb*C + t] - sXq[((row >> 4) << 8) + t] + pr;
            sW[row*260 + t] = fmaxf(s1*w + h1, 0.f);
        }
        __syncthreads();
        {
            ull p0 = 0ull, p1 = 0ull, p2 = 0ull, p3 = 0ull;
            const ulonglong2* rp = (const ulonglong2*)(sW + lane*260);
            const ulonglong2* q0 = (const ulonglong2*)(sWw1 + (warp*4+0)*256);
            const ulonglong2* q1 = (const ulonglong2*)(sWw1 + (warp*4+1)*256);
            const ulonglong2* q2 = (const ulonglong2*)(sWw1 + (warp*4+2)*256);
            const ulonglong2* q3 = (const ulonglong2*)(sWw1 + (warp*4+3)*256);
#pragma unroll 8
            for (int k4 = 0; k4 < 64; k4++) {
                ulonglong2 r = rp[k4];
                ulonglong2 b0 = q0[k4]; fma2(p0, r.x, b0.x); fma2(p0, r.y, b0.y);
                ulonglong2 b1v = q1[k4]; fma2(p1, r.x, b1v.x); fma2(p1, r.y, b1v.y);
                ulonglong2 b2v = q2[k4]; fma2(p2, r.x, b2v.x); fma2(p2, r.y, b2v.y);
                ulonglong2 b3v = q3[k4]; fma2(p3, r.x, b3v.x); fma2(p3, r.y, b3v.y);
            }
            float2 f0 = unpack2(p0), f1 = unpack2(p1), f2 = unpack2(p2), f3 = unpack2(p3);
            sOut[lane*33 + warp*4 + 0] = f0.x + f0.y;
            sOut[lane*33 + warp*4 + 1] = f1.x + f1.y;
            sOut[lane*33 + warp*4 + 2] = f2.x + f2.y;
            sOut[lane*33 + warp*4 + 3] = f3.x + f3.y;
        }
        __syncthreads();
#pragma unroll
        for (int rep = 0; rep < 4; rep++) {
            int linear = rep*256 + t;
            float v = sOut[(linear >> 5)*33 + (linear & 31)] + bwv;
            g_w2[(size_t)iA*512 + linear] = v;
            acc2s += v; acc2ss += v*v;
        }
    }
    __syncthreads();
    sRed[t] = acc2s;
    __syncthreads();
    if (t < 32) {
        float s = 0.f;
#pragma unroll
        for (int r = 0; r < 8; r++) s += sRed[t + r*32];
        atomicAdd(&g_sum_2[t], s);
    }
    __syncthreads();
    sRed[t] = acc2ss;
    __syncthreads();
    if (t < 32) {
        float s = 0.f;
#pragma unroll
        for (int r = 0; r < 8; r++) s += sRed[t + r*32];
        atomicAdd(&g_ssq_2[t], s);
    }
}

// ---------------- launch 5: bn2->relu->ww2->softmax->weighted sum ----------------
__global__ __launch_bounds__(256) void k_out(const int* __restrict__ idx,
                                             const float* __restrict__ gp, const float* __restrict__ btp,
                                             const float* __restrict__ wp2, const float* __restrict__ bp2,
                                             const float* __restrict__ ww2, const float* __restrict__ bw2,
                                             const float* __restrict__ g2, const float* __restrict__ b2,
                                             float* __restrict__ out) {
    __shared__ float sWw2[32][33];
    __shared__ float sU[32][33];
    __shared__ float sW3[32][33];
    __shared__ int   sIdx[32];
    __shared__ float sR3[96];

    const int t = threadIdx.x;
    const int cm = t & 31;
#pragma unroll
    for (int rep = 0; rep < 4; rep++) {
        int linear = rep*256 + t;
        sWw2[linear >> 5][linear & 31] = ww2[linear];
    }
    const float invM = 1.f / (float)MTOT;
    float bs0, bs1, bs2, bh0, bh1, bh2;
    {
        float m0 = g_sum_p[0]*invM, m1 = g_sum_p[1]*invM, m2 = g_sum_p[2]*invM;
        float v0 = fmaxf(g_ssq_p[0]*invM - m0*m0, 0.f);
        float v1 = fmaxf(g_ssq_p[1]*invM - m1*m1, 0.f);
        float v2 = fmaxf(g_ssq_p[2]*invM - m2*m2, 0.f);
        bs0 = gp[0]*rsqrtf(v0+EPS); bh0 = btp[0]-m0*bs0;
        bs1 = gp[1]*rsqrtf(v1+EPS); bh1 = btp[1]-m1*bs1;
        bs2 = gp[2]*rsqrtf(v2+EPS); bh2 = btp[2]-m2*bs2;
    }
    float s2, h2;
    {
        float mean = g_sum_2[cm]*invM;
        float var  = fmaxf(g_ssq_2[cm]*invM - mean*mean, 0.f);
        s2 = g2[cm]*rsqrtf(var+EPS); h2 = b2[cm] - mean*s2;
    }
    const float w20 = wp2[t*3+0], w21 = wp2[t*3+1], w22 = wp2[t*3+2], bpc = bp2[t];
    const float bw2c = bw2[cm];
    const int i0 = blockIdx.x * 16;

    for (int pp = 0; pp < 8; pp++) {
        const int iA = i0 + pp*2;
        __syncthreads();
        if (t < 32) sIdx[t] = idx[iA*NS + t];
        if (t < 96) {
            int d = t % 3;
            float sc = (d==0) ? bs0 : ((d==1) ? bs1 : bs2);
            float hh = (d==0) ? bh0 : ((d==1) ? bh1 : bh2);
            sR3[t] = fmaxf(sc * g_v3[(size_t)iA*48 + t] + hh, 0.f);
        }
#pragma unroll
        for (int rep = 0; rep < 4; rep++) {
            int linear = rep*256 + t;
            float v = g_w2[(size_t)iA*512 + linear];
            sU[linear >> 5][cm] = fmaxf(s2*v + h2, 0.f);
        }
        __syncthreads();
#pragma unroll
        for (int rep = 0; rep < 4; rep++) {
            int linear = rep*256 + t;
            int j = linear >> 5;
            float a = bw2c;
#pragma unroll
            for (int k = 0; k < 32; k++) a += sU[j][k] * sWw2[cm][k];
            sW3[j][cm] = a;
        }
        __syncthreads();
        if (t < 64) {
            int pt = t >> 5, c = t & 31;
            int base = pt * 16;
            float mx = -1e30f;
#pragma unroll
            for (int j = 0; j < NS; j++) mx = fmaxf(mx, sW3[base+j][c]);
            float sum = 0.f;
#pragma unroll
            for (int j = 0; j < NS; j++) { float e = __expf(sW3[base+j][c] - mx); sW3[base+j][c] = e; sum += e; }
            float inv = 1.f / sum;
#pragma unroll
            for (int j = 0; j < NS; j++) sW3[base+j][c] *= inv;
        }
        __syncthreads();
#pragma unroll
        for (int pt = 0; pt < 2; pt++) {
            float acc = 0.f;
#pragma unroll
            for (int j = 0; j < NS; j++) {
                int rj = pt*16 + j;
                int nb = sIdx[rj];
                float pr = w20*sR3[rj*3+0] + w21*sR3[rj*3+1] + w22*sR3[rj*3+2] + bpc;
                acc += (g_xv[(size_t)nb*C + t] + pr) * sW3[rj][cm];
            }
            out[(size_t)(iA+pt)*C + t] = acc;
        }
    }
}

// ---------------- launch ----------------
extern "C" void kernel_launch(void* const* d_in, const int* in_sizes, int n_in,
                              void* d_out, int out_size) {
    const float* p   = (const float*)d_in[0];
    const float* x   = (const float*)d_in[1];
    const int*   idx = (const int*)d_in[2];
    const float* wq  = (const float*)d_in[3];
    const float* bq  = (const float*)d_in[4];
    const float* wk  = (const float*)d_in[5];
    const float* bk  = (const float*)d_in[6];
    const float* wv  = (const float*)d_in[7];
    const float* bv  = (const float*)d_in[8];
    const float* wp1 = (const float*)d_in[9];
    const float* bp1 = (const float*)d_in[10];
    const float* gp  = (const float*)d_in[11];
    const float* btp = (const float*)d_in[12];
    const float* wp2 = (const float*)d_in[13];
    const float* bp2 = (const float*)d_in[14];
    const float* g1  = (const float*)d_in[15];
    const float* b1  = (const float*)d_in[16];
    const float* ww1 = (const float*)d_in[17];
    const float* bw1 = (const float*)d_in[18];
    const float* g2  = (const float*)d_in[19];
    const float* b2  = (const float*)d_in[20];
    const float* ww2 = (const float*)d_in[21];
    const float* bw2 = (const float*)d_in[22];
    float* out = (float*)d_out;

    cudaFuncSetAttribute(k_w2, cudaFuncAttributeMaxDynamicSharedMemorySize,
                         K6_SMEM_FLOATS * (int)sizeof(float));

    k_zero<<<1, 256>>>();
    k_qkv_statp<<<dim3(7, 512), 256>>>(x, p, idx, wq, bq, wk, bk, wv, bv, wp1, bp1);
    k_stat1<<<4096, 256>>>(idx, gp, btp, wp2, bp2);
    k_w2<<<2048, 256, K6_SMEM_FLOATS * sizeof(float)>>>(idx, gp, btp, wp2, bp2, ww1, bw1, g1, b1);
    k_out<<<4096, 256>>>(idx, gp, btp, wp2, bp2, ww2, bw2, g2, b2, out);
}

// round 8
// speedup vs baseline: 1.3563x; 1.3412x over previous
#include <cuda_runtime.h>
#include <math.h>

#define NPTS 65536
#define NS 16
#define C 256
#define MTOT (NPTS*NS)
#define EPS 1e-5f

typedef unsigned long long ull;

__device__ __forceinline__ ull pack2(float lo, float hi) {
    ull r; asm("mov.b64 %0, {%1, %2};" : "=l"(r) : "f"(lo), "f"(hi)); return r;
}
__device__ __forceinline__ void fma2(ull& d, ull a, ull b) {
    asm("fma.rn.f32x2 %0, %1, %2, %3;" : "=l"(d) : "l"(a), "l"(b), "l"(d));
}
__device__ __forceinline__ float2 unpack2(ull v) {
    float2 f; asm("mov.b64 {%0, %1}, %2;" : "=f"(f.x), "=f"(f.y) : "l"(v)); return f;
}

__device__ float g_xq[NPTS*C];
__device__ float g_xk[NPTS*C];
__device__ float g_xv[NPTS*C];
__device__ float g_w2[NPTS*NS*32];
__device__ float g_v3[MTOT*3];
__device__ float g_sum_p[3], g_ssq_p[3];
__device__ float g_sum_1[C], g_ssq_1[C];
__device__ float g_sum_2[32], g_ssq_2[32];

__global__ void k_zero() {
    int t = threadIdx.x;
    if (t < 3)  { g_sum_p[t] = 0.f; g_ssq_p[t] = 0.f; }
    if (t < C)  { g_sum_1[t] = 0.f; g_ssq_1[t] = 0.f; }
    if (t < 32) { g_sum_2[t] = 0.f; g_ssq_2[t] = 0.f; }
}

// ---------------- qkv SGEMM (FFMA2) + fused statp/v3 ----------------
__global__ __launch_bounds__(256) void k_qkv_statp(
        const float* __restrict__ x, const float* __restrict__ p,
        const int* __restrict__ idx,
        const float* __restrict__ wq, const float* __restrict__ bq,
        const float* __restrict__ wk, const float* __restrict__ bk,
        const float* __restrict__ wv, const float* __restrict__ bv,
        const float* __restrict__ wp1, const float* __restrict__ bp1) {
    const int t = threadIdx.x;
    if (blockIdx.x == 6) {
        float W[9], B[3];
#pragma unroll
        for (int q = 0; q < 9; q++) W[q] = wp1[q];
#pragma unroll
        for (int q = 0; q < 3; q++) B[q] = bp1[q];
        float s[3] = {0,0,0}, ss[3] = {0,0,0};
        for (int m = blockIdx.y*256 + t; m < MTOT; m += 512*256) {
            int i = m >> 4;
            int nb = idx[m];
            float d0 = p[nb*3+0]-p[i*3+0], d1 = p[nb*3+1]-p[i*3+1], d2 = p[nb*3+2]-p[i*3+2];
#pragma unroll
            for (int d = 0; d < 3; d++) {
                float v = W[d*3+0]*d0 + W[d*3+1]*d1 + W[d*3+2]*d2 + B[d];
                g_v3[(size_t)m*3 + d] = v;
                s[d] += v; ss[d] += v*v;
            }
        }
#pragma unroll
        for (int off = 16; off > 0; off >>= 1)
#pragma unroll
            for (int d = 0; d < 3; d++) {
                s[d]  += __shfl_down_sync(0xffffffffu, s[d],  off);
                ss[d] += __shfl_down_sync(0xffffffffu, ss[d], off);
            }
        if ((t & 31) == 0)
#pragma unroll
            for (int d = 0; d < 3; d++) {
                atomicAdd(&g_sum_p[d], s[d]); atomicAdd(&g_ssq_p[d], ss[d]);
            }
        return;
    }
    __shared__ float As[16][132];
    __shared__ float Bs[16][132];
    const int tx = t & 15, ty = t >> 4;
    const int m0 = blockIdx.y * 128, n0 = blockIdx.x * 128;
    const float* wsel; const float* bsel; float* dst;
    if (n0 < 256)      { wsel = wq; bsel = bq; dst = g_xq; }
    else if (n0 < 512) { wsel = wk; bsel = bk; dst = g_xk; }
    else               { wsel = wv; bsel = bv; dst = g_xv; }
    const int rb = n0 & 255;
    ull acc2[8][4];
#pragma unroll
    for (int ii = 0; ii < 8; ii++)
#pragma unroll
        for (int jj = 0; jj < 4; jj++) acc2[ii][jj] = 0ull;
    const int lrow = t >> 2, lk4 = (t & 3) << 2;
    for (int k0 = 0; k0 < 256; k0 += 16) {
#pragma unroll
        for (int h = 0; h < 2; h++) {
            int r = lrow + h*64;
            float4 va = *(const float4*)(x + (size_t)(m0 + r)*256 + k0 + lk4);
            As[lk4+0][r] = va.x; As[lk4+1][r] = va.y; As[lk4+2][r] = va.z; As[lk4+3][r] = va.w;
            float4 vb = *(const float4*)(wsel + (size_t)(rb + r)*256 + k0 + lk4);
            Bs[lk4+0][r] = vb.x; Bs[lk4+1][r] = vb.y; Bs[lk4+2][r] = vb.z; Bs[lk4+3][r] = vb.w;
        }
        __syncthreads();
#pragma unroll
        for (int k = 0; k < 16; k++) {
            float a[8];
            *(float4*)&a[0] = *(const float4*)&As[k][ty*4];
            *(float4*)&a[4] = *(const float4*)&As[k][ty*4 + 64];
            ull b2[4];
            {
                ulonglong2 u0 = *(const ulonglong2*)&Bs[k][tx*4];
                ulonglong2 u1 = *(const ulonglong2*)&Bs[k][tx*4 + 64];
                b2[0] = u0.x; b2[1] = u0.y; b2[2] = u1.x; b2[3] = u1.y;
            }
            ull a2[8];
#pragma unroll
            for (int ii = 0; ii < 8; ii++) a2[ii] = pack2(a[ii], a[ii]);
#pragma unroll
            for (int ii = 0; ii < 8; ii++)
#pragma unroll
                for (int jj = 0; jj < 4; jj++) fma2(acc2[ii][jj], a2[ii], b2[jj]);
        }
        __syncthreads();
    }
    float bias[8];
#pragma unroll
    for (int jj = 0; jj < 8; jj++)
        bias[jj] = bsel[rb + tx*4 + ((jj >> 2) << 6) + (jj & 3)];
#pragma unroll
    for (int ii = 0; ii < 8; ii++) {
        int row = m0 + ty*4 + (ii & 3) + ((ii >> 2) << 6);
#pragma unroll
        for (int jh = 0; jh < 2; jh++) {
            float2 lo = unpack2(acc2[ii][jh*2]);
            float2 hi = unpack2(acc2[ii][jh*2+1]);
            float4 o = {lo.x + bias[jh*4], lo.y + bias[jh*4+1], hi.x + bias[jh*4+2], hi.y + bias[jh*4+3]};
            *(float4*)(dst + (size_t)row*256 + rb + tx*4 + (jh << 6)) = o;
        }
    }
}

// ---------------- BN1 stats: float4 gathers, 64 thr/point ----------------
__global__ __launch_bounds__(256) void k_stat1(const int* __restrict__ idx,
        const float* __restrict__ gp, const float* __restrict__ btp,
        const float* __restrict__ wp2, const float* __restrict__ bp2) {
    __shared__ float sR3[4][48];
    __shared__ int   sIdxs[4][16];
    __shared__ float sTmp[2048];
    const int t = threadIdx.x;
    const int sub = t >> 6, cg = t & 63, c0 = cg << 2;
    const float invM = 1.f / (float)MTOT;
    float bns[3], bnh[3];
#pragma unroll
    for (int d = 0; d < 3; d++) {
        float m = g_sum_p[d]*invM;
        float v = fmaxf(g_ssq_p[d]*invM - m*m, 0.f);
        bns[d] = gp[d]*rsqrtf(v+EPS); bnh[d] = btp[d] - m*bns[d];
    }
    float w20[4], w21[4], w22[4], bpc[4];
#pragma unroll
    for (int q = 0; q < 4; q++) {
        w20[q] = wp2[(c0+q)*3+0]; w21[q] = wp2[(c0+q)*3+1]; w22[q] = wp2[(c0+q)*3+2];
        bpc[q] = bp2[c0+q];
    }
    float s[4] = {0,0,0,0}, ss[4] = {0,0,0,0};
    const int i0 = blockIdx.x * 16;
    for (int it = 0; it < 4; it++) {
        const int i = i0 + it*4 + sub;
        __syncthreads();
        if (cg < 16) sIdxs[sub][cg] = idx[i*NS + cg];
        else if (cg < 32) {
            int j = cg - 16;
            const float* vp = g_v3 + ((size_t)i*NS + j)*3;
            sR3[sub][j*3+0] = fmaxf(bns[0]*vp[0] + bnh[0], 0.f);
            sR3[sub][j*3+1] = fmaxf(bns[1]*vp[1] + bnh[1], 0.f);
            sR3[sub][j*3+2] = fmaxf(bns[2]*vp[2] + bnh[2], 0.f);
        }
        __syncthreads();
        float4 xq4 = __ldg((const float4*)(g_xq + (size_t)i*C + c0));
#pragma unroll
        for (int j = 0; j < 16; j++) {
            int nb = sIdxs[sub][j];
            float r0 = sR3[sub][j*3], r1 = sR3[sub][j*3+1], r2 = sR3[sub][j*3+2];
            float4 xk4 = __ldg((const float4*)(g_xk + (size_t)nb*C + c0));
            float w;
            w = xk4.x - xq4.x + w20[0]*r0 + w21[0]*r1 + w22[0]*r2 + bpc[0]; s[0] += w; ss[0] += w*w;
            w = xk4.y - xq4.y + w20[1]*r0 + w21[1]*r1 + w22[1]*r2 + bpc[1]; s[1] += w; ss[1] += w*w;
            w = xk4.z - xq4.z + w20[2]*r0 + w21[2]*r1 + w22[2]*r2 + bpc[2]; s[2] += w; ss[2] += w*w;
            w = xk4.w - xq4.w + w20[3]*r0 + w21[3]*r1 + w22[3]*r2 + bpc[3]; s[3] += w; ss[3] += w*w;
        }
    }
    __syncthreads();
#pragma unroll
    for (int q = 0; q < 4; q++) {
        sTmp[sub*256 + c0 + q] = s[q];
        sTmp[1024 + sub*256 + c0 + q] = ss[q];
    }
    __syncthreads();
    float a = sTmp[t] + sTmp[256+t] + sTmp[512+t] + sTmp[768+t];
    atomicAdd(&g_sum_1[t], a);
    float b = sTmp[1024+t] + sTmp[1280+t] + sTmp[1536+t] + sTmp[1792+t];
    atomicAdd(&g_ssq_1[t], b);
}

// ---------------- w2 GEMM: 64-row tiles, register-tiled FFMA2 ----------------
// smem floats: sW[64*260]=16640 | sB[32*260]=8320 | sXq[1024] | sR3[192] | sIdx[64]
#define K6_SMEM_FLOATS (16640 + 8320 + 1024 + 192 + 64)
__global__ __launch_bounds__(256) void k_w2(const int* __restrict__ idx,
        const float* __restrict__ gp, const float* __restrict__ btp,
        const float* __restrict__ wp2, const float* __restrict__ bp2,
        const float* __restrict__ ww1, const float* __restrict__ bw1,
        const float* __restrict__ g1, const float* __restrict__ b1) {
    extern __shared__ float sm[];
    float* sW  = sm;
    float* sB  = sm + 16640;
    float* sXq = sm + 24960;
    float* sR3 = sm + 25984;
    int*   sIdx = (int*)(sm + 26176);
    const int t = threadIdx.x;
    for (int e = t; e < 8192; e += 256) sB[(e>>8)*260 + (e&255)] = ww1[e];
    const int rgrp = t >> 6, cg = t & 63, c0 = cg << 2;
    const float invM = 1.f / (float)MTOT;
    float bns[3], bnh[3];
#pragma unroll
    for (int d = 0; d < 3; d++) {
        float m = g_sum_p[d]*invM;
        float v = fmaxf(g_ssq_p[d]*invM - m*m, 0.f);
        bns[d] = gp[d]*rsqrtf(v+EPS); bnh[d] = btp[d] - m*bns[d];
    }
    float s1[4], h1[4], w20[4], w21[4], w22[4], bpc[4];
#pragma unroll
    for (int q = 0; q < 4; q++) {
        float mean = g_sum_1[c0+q]*invM;
        float var  = fmaxf(g_ssq_1[c0+q]*invM - mean*mean, 0.f);
        s1[q] = g1[c0+q]*rsqrtf(var+EPS); h1[q] = b1[c0+q] - mean*s1[q];
        w20[q] = wp2[(c0+q)*3+0]; w21[q] = wp2[(c0+q)*3+1]; w22[q] = wp2[(c0+q)*3+2];
        bpc[q] = bp2[c0+q];
    }
    const int r2 = t >> 3, og = t & 7;
    float bwv[4];
#pragma unroll
    for (int oo = 0; oo < 4; oo++) bwv[oo] = bw1[og + 8*oo];
    float acs[4] = {0,0,0,0}, acss[4] = {0,0,0,0};
    const int i0 = blockIdx.x * 32;

    for (int pp = 0; pp < 8; pp++) {
        const int iB = i0 + pp*4;
        __syncthreads();
        if (t < 64) sIdx[t] = idx[iB*NS + t];
        else {
            int m = t - 64, d = m % 3;
            sR3[m] = fmaxf(bns[d]*g_v3[(size_t)iB*48 + m] + bnh[d], 0.f);
        }
        ((float4*)sXq)[t] = __ldg((const float4*)(g_xq + (size_t)(iB + (t>>6))*C) + (t & 63));
        __syncthreads();
#pragma unroll 4
        for (int m = 0; m < 16; m++) {
            int row = m*4 + rgrp;
            int nb = sIdx[row];
            float r0 = sR3[row*3], r1 = sR3[row*3+1], rr2 = sR3[row*3+2];
            float4 xk4 = __ldg((const float4*)(g_xk + (size_t)nb*C + c0));
            const float4 xq4 = *(const float4*)(sXq + ((row >> 4) << 8) + c0);
            float4 u;
            u.x = fmaxf(s1[0]*(xk4.x - xq4.x + w20[0]*r0 + w21[0]*r1 + w22[0]*rr2 + bpc[0]) + h1[0], 0.f);
            u.y = fmaxf(s1[1]*(xk4.y - xq4.y + w20[1]*r0 + w21[1]*r1 + w22[1]*rr2 + bpc[1]) + h1[1], 0.f);
            u.z = fmaxf(s1[2]*(xk4.z - xq4.z + w20[2]*r0 + w21[2]*r1 + w22[2]*rr2 + bpc[2]) + h1[2], 0.f);
            u.w = fmaxf(s1[3]*(xk4.w - xq4.w + w20[3]*r0 + w21[3]*r1 + w22[3]*rr2 + bpc[3]) + h1[3], 0.f);
            *(float4*)(sW + row*260 + c0) = u;
        }
        __syncthreads();
        ull a0[4] = {0,0,0,0}, a1[4] = {0,0,0,0};
        const ulonglong2* pa = (const ulonglong2*)(sW + r2*260);
        const ulonglong2* pb = (const ulonglong2*)(sW + (r2+32)*260);
        const ulonglong2* pw0 = (const ulonglong2*)(sB + og*260);
        const ulonglong2* pw1 = (const ulonglong2*)(sB + (og+8)*260);
        const ulonglong2* pw2 = (const ulonglong2*)(sB + (og+16)*260);
        const ulonglong2* pw3 = (const ulonglong2*)(sB + (og+24)*260);
#pragma unroll 8
        for (int k4 = 0; k4 < 64; k4++) {
            ulonglong2 av = pa[k4], bv = pb[k4];
            ulonglong2 w0 = pw0[k4];
            fma2(a0[0], av.x, w0.x); fma2(a0[0], av.y, w0.y);
            fma2(a1[0], bv.x, w0.x); fma2(a1[0], bv.y, w0.y);
            ulonglong2 w1 = pw1[k4];
            fma2(a0[1], av.x, w1.x); fma2(a0[1], av.y, w1.y);
            fma2(a1[1], bv.x, w1.x); fma2(a1[1], bv.y, w1.y);
            ulonglong2 w2 = pw2[k4];
            fma2(a0[2], av.x, w2.x); fma2(a0[2], av.y, w2.y);
            fma2(a1[2], bv.x, w2.x); fma2(a1[2], bv.y, w2.y);
            ulonglong2 w3 = pw3[k4];
            fma2(a0[3], av.x, w3.x); fma2(a0[3], av.y, w3.y);
            fma2(a1[3], bv.x, w3.x); fma2(a1[3], bv.y, w3.y);
        }
#pragma unroll
        for (int oo = 0; oo < 4; oo++) {
            int oc = og + 8*oo;
            float2 f0 = unpack2(a0[oo]);
            float v0 = f0.x + f0.y + bwv[oo];
            float2 f1 = unpack2(a1[oo]);
            float v1 = f1.x + f1.y + bwv[oo];
            g_w2[(size_t)iB*512 + r2*32 + oc] = v0;
            g_w2[(size_t)iB*512 + (r2+32)*32 + oc] = v1;
            acs[oo] += v0 + v1; acss[oo] += v0*v0 + v1*v1;
        }
    }
    __syncthreads();
#pragma unroll
    for (int oo = 0; oo < 4; oo++) {
        sW[t*4 + oo] = acs[oo];
        sW[1024 + t*4 + oo] = acss[oo];
    }
    __syncthreads();
    if (t < 32) {
        int g = t & 7, v = t >> 3;
        float a = 0.f, b = 0.f;
#pragma unroll 8
        for (int u = 0; u < 32; u++) {
            a += sW[(g + 8*u)*4 + v];
            b += sW[1024 + (g + 8*u)*4 + v];
        }
        atomicAdd(&g_sum_2[t], a);
        atomicAdd(&g_ssq_2[t], b);
    }
}

// ---------------- bn2->relu->ww2(regs)->softmax->weighted sum ----------------
__global__ __launch_bounds__(256) void k_out(const int* __restrict__ idx,
        const float* __restrict__ gp, const float* __restrict__ btp,
        const float* __restrict__ wp2, const float* __restrict__ bp2,
        const float* __restrict__ ww2, const float* __restrict__ bw2,
        const float* __restrict__ g2, const float* __restrict__ b2,
        float* __restrict__ out) {
    __shared__ float sU[32*34];
    __shared__ float sW3[32*33];
    __shared__ int   sIdx[32];
    __shared__ float sR3[96];
    const int t = threadIdx.x;
    const int cm = t & 31;
    const float invM = 1.f / (float)MTOT;
    float s2, h2;
    {
        float m = g_sum_2[cm]*invM;
        float v = fmaxf(g_ssq_2[cm]*invM - m*m, 0.f);
        s2 = g2[cm]*rsqrtf(v+EPS); h2 = b2[cm] - m*s2;
    }
    ull wreg[16];
    {
        const ulonglong2* wp = (const ulonglong2*)(ww2 + cm*32);
#pragma unroll
        for (int q = 0; q < 8; q++) {
            ulonglong2 v = __ldg(wp + q);
            wreg[q*2] = v.x; wreg[q*2+1] = v.y;
        }
    }
    const float bw2c = bw2[cm];
    float bns[3], bnh[3];
#pragma unroll
    for (int d = 0; d < 3; d++) {
        float m = g_sum_p[d]*invM;
        float v = fmaxf(g_ssq_p[d]*invM - m*m, 0.f);
        bns[d] = gp[d]*rsqrtf(v+EPS); bnh[d] = btp[d] - m*bns[d];
    }
    const float w20 = wp2[t*3+0], w21 = wp2[t*3+1], w22 = wp2[t*3+2], bpc = bp2[t];
    const int i0 = blockIdx.x * 16;

    for (int pp = 0; pp < 8; pp++) {
        const int iA = i0 + pp*2;
        __syncthreads();
        if (t < 32) sIdx[t] = idx[iA*NS + t];
        else if (t < 128) {
            int m = t - 32, d = m % 3;
            sR3[m] = fmaxf(bns[d]*g_v3[(size_t)iA*48 + m] + bnh[d], 0.f);
        }
        // stage BOTH points' w2 (1024 floats = 32 rows x 32 ch)
#pragma unroll
        for (int rep = 0; rep < 4; rep++) {
            int linear = rep*256 + t;
            float v = g_w2[(size_t)iA*512 + linear];
            sU[(linear >> 5)*34 + cm] = fmaxf(s2*v + h2, 0.f);
        }
        __syncthreads();
#pragma unroll
        for (int rep = 0; rep < 4; rep++) {
            int jrow = rep*8 + (t >> 5);
            const ull* up = (const ull*)(sU + jrow*34);
            ull acc = 0ull;
#pragma unroll
            for (int k2 = 0; k2 < 16; k2++) fma2(acc, up[k2], wreg[k2]);
            float2 f = unpack2(acc);
            sW3[jrow*33 + cm] = f.x + f.y + bw2c;
        }
        __syncthreads();
        if (t < 64) {
            int pt = t >> 5, c = t & 31;
            int base = pt * 16;
            float mx = -1e30f;
#pragma unroll
            for (int j = 0; j < 16; j++) mx = fmaxf(mx, sW3[(base+j)*33 + c]);
            float sum = 0.f;
#pragma unroll
            for (int j = 0; j < 16; j++) {
                float e = __expf(sW3[(base+j)*33 + c] - mx);
                sW3[(base+j)*33 + c] = e; sum += e;
            }
            float inv = 1.f / sum;
#pragma unroll
            for (int j = 0; j < 16; j++) sW3[(base+j)*33 + c] *= inv;
        }
        __syncthreads();
#pragma unroll
        for (int pt = 0; pt < 2; pt++) {
            float acc = 0.f;
#pragma unroll
            for (int j = 0; j < 16; j++) {
                int rj = pt*16 + j;
                int nb = sIdx[rj];
                float pr = w20*sR3[rj*3] + w21*sR3[rj*3+1] + w22*sR3[rj*3+2] + bpc;
                acc += (g_xv[(size_t)nb*C + t] + pr) * sW3[rj*33 + cm];
            }
            out[(size_t)(iA+pt)*C + t] = acc;
        }
    }
}

extern "C" void kernel_launch(void* const* d_in, const int* in_sizes, int n_in,
                              void* d_out, int out_size) {
    const float* p   = (const float*)d_in[0];
    const float* x   = (const float*)d_in[1];
    const int*   idx = (const int*)d_in[2];
    const float* wq  = (const float*)d_in[3];
    const float* bq  = (const float*)d_in[4];
    const float* wk  = (const float*)d_in[5];
    const float* bk  = (const float*)d_in[6];
    const float* wv  = (const float*)d_in[7];
    const float* bv  = (const float*)d_in[8];
    const float* wp1 = (const float*)d_in[9];
    const float* bp1 = (const float*)d_in[10];
    const float* gp  = (const float*)d_in[11];
    const float* btp = (const float*)d_in[12];
    const float* wp2 = (const float*)d_in[13];
    const float* bp2 = (const float*)d_in[14];
    const float* g1  = (const float*)d_in[15];
    const float* b1  = (const float*)d_in[16];
    const float* ww1 = (const float*)d_in[17];
    const float* bw1 = (const float*)d_in[18];
    const float* g2  = (const float*)d_in[19];
    const float* b2  = (const float*)d_in[20];
    const float* ww2 = (const float*)d_in[21];
    const float* bw2 = (const float*)d_in[22];
    float* out = (float*)d_out;

    cudaFuncSetAttribute(k_w2, cudaFuncAttributeMaxDynamicSharedMemorySize,
                         K6_SMEM_FLOATS * (int)sizeof(float));

    k_zero<<<1, 256>>>();
    k_qkv_statp<<<dim3(7, 512), 256>>>(x, p, idx, wq, bq, wk, bk, wv, bv, wp1, bp1);
    k_stat1<<<4096, 256>>>(idx, gp, btp, wp2, bp2);
    k_w2<<<2048, 256, K6_SMEM_FLOATS * sizeof(float)>>>(idx, gp, btp, wp2, bp2, ww1, bw1, g1, b1);
    k_out<<<4096, 256>>>(idx, gp, btp, wp2, bp2, ww2, bw2, g2, b2, out);
}